// round 15
// baseline (speedup 1.0000x reference)
#include <cuda_runtime.h>
#include <cuda_fp16.h>
#include <math.h>
#include <stdint.h>

// Problem constants
#define BB   2
#define NN   2048
#define HIDD 2048
#define NH   16
#define NKV  4
#define DD   128
#define MQ   (BB*NN)        // 4096
#define DQ   (NH*DD)        // 2048
#define DKV  (NKV*DD)       // 512
#define NQKV (DQ + 2*DKV)   // 3072

// ---------------- device scratch ------------------------------------------
__device__ __half g_Xh  [(size_t)MQ * HIDD];
__device__ __half g_QKV [(size_t)MQ * NQKV];
__device__ __half g_AOh [(size_t)MQ * DQ];
__device__ __half g_WTa [(size_t)NQKV * HIDD];
__device__ __half g_WTo [(size_t)HIDD * DQ];
__device__ float  g_FLA [(size_t)MQ * HIDD];
__device__ int    g_cntRT[32];      // per row-tile QKV completion (24 each)
__device__ int    g_cntFlash[32];   // per (b,qi) flash completion (16 each)

// ---------------- helpers --------------------------------------------------
__device__ __forceinline__ void mma_h16(float* c, const uint32_t* a, const uint32_t* b) {
    asm volatile(
        "mma.sync.aligned.m16n8k16.row.col.f32.f16.f16.f32 "
        "{%0,%1,%2,%3}, {%4,%5,%6,%7}, {%8,%9}, {%0,%1,%2,%3};\n"
        : "+f"(c[0]), "+f"(c[1]), "+f"(c[2]), "+f"(c[3])
        : "r"(a[0]), "r"(a[1]), "r"(a[2]), "r"(a[3]),
          "r"(b[0]), "r"(b[1]));
}
__device__ __forceinline__ void ldsm4(uint32_t& r0, uint32_t& r1, uint32_t& r2,
                                      uint32_t& r3, uint32_t addr) {
    asm volatile("ldmatrix.sync.aligned.m8n8.x4.shared.b16 {%0,%1,%2,%3}, [%4];"
                 : "=r"(r0), "=r"(r1), "=r"(r2), "=r"(r3) : "r"(addr));
}
__device__ __forceinline__ void cp16(void* smem, const void* gmem) {
    uint32_t s = (uint32_t)__cvta_generic_to_shared(smem);
    asm volatile("cp.async.cg.shared.global [%0], [%1], 16;\n" :: "r"(s), "l"(gmem));
}
__device__ __forceinline__ void cp_commit() { asm volatile("cp.async.commit_group;\n"); }
template<int N8>
__device__ __forceinline__ void cp_wait() { asm volatile("cp.async.wait_group %0;\n" :: "n"(N8)); }
__device__ __forceinline__ uint32_t h2u(__half2 h) { return *reinterpret_cast<uint32_t*>(&h); }

// tid-0-only spin (R10-proven) — call from ALL threads.
__device__ __forceinline__ void spin0(int* p, int need) {
    if (threadIdx.x == 0) {
        while (atomicAdd(p, 0) < need) __nanosleep(256);
    }
    __syncthreads();
    __threadfence();
}

// ---------------- merged prepass kernel ------------------------------------
#define PB_CONV 8192
#define PB_WQ   4096
#define PB_WKV  1024
#define PB_WO   4096
#define PREP_BLOCKS (PB_CONV + PB_WQ + 2*PB_WKV + PB_WO + 1)

__device__ __forceinline__ void transh_dev(const float* __restrict__ W,
        __half* __restrict__ WT, int K, int N, float alpha, int bx, int by,
        float (*t)[33])
{
    int k0 = by * 32, n0 = bx * 32;
    int tx = threadIdx.x & 31, ty = threadIdx.x >> 5;
#pragma unroll
    for (int i = 0; i < 4; i++)
        t[ty + 8 * i][tx] = W[(long)(k0 + ty + 8 * i) * N + n0 + tx];
    __syncthreads();
#pragma unroll
    for (int i = 0; i < 4; i++)
        WT[(long)(n0 + ty + 8 * i) * K + k0 + tx] = __float2half_rn(alpha * t[tx][ty + 8 * i]);
}

__global__ __launch_bounds__(256)
void prep_k(const float* __restrict__ hid,
            const float* __restrict__ Wq, const float* __restrict__ Wk,
            const float* __restrict__ Wv, const float* __restrict__ Wo,
            __half* __restrict__ Xh, __half* __restrict__ WTa,
            __half* __restrict__ WTo, float scale)
{
    __shared__ float t[32][33];
    const int bid = blockIdx.x;

    if (bid < PB_CONV) {
        int i = bid * 256 + threadIdx.x;
        float4 v = ((const float4*)hid)[i];
        uint2 o;
        o.x = h2u(__floats2half2_rn(v.x, v.y));
        o.y = h2u(__floats2half2_rn(v.z, v.w));
        ((uint2*)Xh)[i] = o;
    } else if (bid < PB_CONV + PB_WQ) {
        int tbid = bid - PB_CONV;
        transh_dev(Wq, WTa, HIDD, DQ, scale, tbid & 63, tbid >> 6, t);
    } else if (bid < PB_CONV + PB_WQ + PB_WKV) {
        int tbid = bid - PB_CONV - PB_WQ;
        transh_dev(Wk, WTa + (size_t)DQ * HIDD, HIDD, DKV, 1.f,
                   tbid & 15, tbid >> 4, t);
    } else if (bid < PB_CONV + PB_WQ + 2 * PB_WKV) {
        int tbid = bid - PB_CONV - PB_WQ - PB_WKV;
        transh_dev(Wv, WTa + (size_t)(DQ + DKV) * HIDD, HIDD, DKV, 1.f,
                   tbid & 15, tbid >> 4, t);
    } else if (bid < PB_CONV + PB_WQ + 2 * PB_WKV + PB_WO) {
        int tbid = bid - PB_CONV - PB_WQ - 2 * PB_WKV;
        transh_dev(Wo, WTo, DQ, HIDD, 1.f, tbid & 63, tbid >> 6, t);
    } else {
        if (threadIdx.x < 32) {
            g_cntFlash[threadIdx.x] = 0;
            g_cntRT[threadIdx.x] = 0;
        }
    }
}

// ---------------- GEMM tile core -------------------------------------------
#define HP    20
#define HSTGW (128*HP)
#define GEMM_SMEMH (4*2*HSTGW*4)

__device__ __forceinline__ void gemm_tile(char* smbuf,
        const __half* __restrict__ Ag, const __half* __restrict__ Bt,
        int Kdim, int rowA0, int colB0, float acc[16][4])
{
    uint32_t* smw = (uint32_t*)smbuf;
    uint32_t* Asb = smw;
    uint32_t* Bsb = smw + 4 * HSTGW;
    const uint32_t abase = (uint32_t)__cvta_generic_to_shared(Asb);
    const uint32_t bbase = (uint32_t)__cvta_generic_to_shared(Bsb);

    const int tid  = threadIdx.x;
    const int lane = tid & 31;
    const int wid  = tid >> 5;
    const int wm   = wid >> 2;
    const int wn   = wid & 3;

    const int niter = Kdim / 32;
    const int lrow  = lane & 15;
    const int lcolw = (lane >> 4) * 4;
    const uint32_t aoff = (uint32_t)(((wm * 64 + lrow) * HP + lcolw) * 4);
    const uint32_t boff = (uint32_t)(((wn * 32 + lrow) * HP + lcolw) * 4);

    const int r0 = tid >> 2,         s0 = (tid & 3);
    const int r1 = (tid + 256) >> 2, s1 = ((tid + 256) & 3);

#pragma unroll
    for (int s = 0; s < 3; s++) {
        int k0 = s * 32;
        uint32_t* As = Asb + s * HSTGW;
        uint32_t* Bs = Bsb + s * HSTGW;
        cp16(&As[r0 * HP + s0 * 4], Ag + (size_t)(rowA0 + r0) * Kdim + k0 + s0 * 8);
        cp16(&As[r1 * HP + s1 * 4], Ag + (size_t)(rowA0 + r1) * Kdim + k0 + s1 * 8);
        cp16(&Bs[r0 * HP + s0 * 4], Bt + (size_t)(colB0 + r0) * Kdim + k0 + s0 * 8);
        cp16(&Bs[r1 * HP + s1 * 4], Bt + (size_t)(colB0 + r1) * Kdim + k0 + s1 * 8);
        cp_commit();
    }

#pragma unroll
    for (int i = 0; i < 16; i++)
#pragma unroll
        for (int j = 0; j < 4; j++) acc[i][j] = 0.f;

    for (int i = 0; i < niter; i++) {
        cp_wait<2>();
        __syncthreads();
        if (i + 3 < niter) {
            int st = (i + 3) & 3;
            int k0 = (i + 3) * 32;
            uint32_t* As = Asb + st * HSTGW;
            uint32_t* Bs = Bsb + st * HSTGW;
            cp16(&As[r0 * HP + s0 * 4], Ag + (size_t)(rowA0 + r0) * Kdim + k0 + s0 * 8);
            cp16(&As[r1 * HP + s1 * 4], Ag + (size_t)(rowA0 + r1) * Kdim + k0 + s1 * 8);
            cp16(&Bs[r0 * HP + s0 * 4], Bt + (size_t)(colB0 + r0) * Kdim + k0 + s0 * 8);
            cp16(&Bs[r1 * HP + s1 * 4], Bt + (size_t)(colB0 + r1) * Kdim + k0 + s1 * 8);
        }
        cp_commit();

        const uint32_t ast = abase + (uint32_t)((i & 3) * HSTGW * 4);
        const uint32_t bst = bbase + (uint32_t)((i & 3) * HSTGW * 4);

#pragma unroll
        for (int ks = 0; ks < 2; ks++) {
            const int k2 = ks * 8;
            uint32_t a[4][4], bf[4][2];
#pragma unroll
            for (int mt = 0; mt < 4; mt++)
                ldsm4(a[mt][0], a[mt][1], a[mt][2], a[mt][3],
                      ast + aoff + (uint32_t)((mt * 16 * HP + k2) * 4));
#pragma unroll
            for (int p = 0; p < 2; p++) {
                uint32_t q0, q1, q2, q3;
                ldsm4(q0, q1, q2, q3, bst + boff + (uint32_t)((p * 16 * HP + k2) * 4));
                bf[2 * p][0] = q0;     bf[2 * p][1] = q2;
                bf[2 * p + 1][0] = q1; bf[2 * p + 1][1] = q3;
            }
#pragma unroll
            for (int mt = 0; mt < 4; mt++)
#pragma unroll
                for (int nt = 0; nt < 4; nt++)
                    mma_h16(acc[mt * 4 + nt], a[mt], bf[nt]);
        }
    }
}

// ---------------- launch 1: QKV GEMM + FLA ---------------------------------
// grid 896: [0,768) QKV tiles (signal g_cntRT); [768,896) FLA (spin g_cntRT)
#define NQK  768
#define NFLA 128

struct FlaSmem {
    float ks[8][128];
    float gs[8][128];
    float qs[4][8][128];
    float vs[8][8];
    float os[8][4][8];
};

__device__ void fla_part(char* smbuf, const __half* Q, const __half* K,
                         const __half* V, int bid)
{
    FlaSmem* sm = (FlaSmem*)smbuf;
    const int et  = bid & 15;
    const int kvh = (bid >> 4) & 3;
    const int b   = bid >> 6;
    const int e0  = et * 8;
    const int tid = threadIdx.x;
    const int lane = tid & 31;
    const int w    = tid >> 5;

    float s0 = 0.f, s1 = 0.f, s2 = 0.f, s3 = 0.f;
    const float CSC = 0.01f;

    for (int c = 0; c < 256; c++) {
        const int n0 = c * 8;
        if ((c & 15) == 0)
            spin0(&g_cntRT[(b << 4) + (c >> 4)], 24);
#pragma unroll
        for (int i = 0; i < 4; i++) {
            int id = tid + i * 256;
            int hh = id >> 8, t = (id >> 5) & 7, d4 = (id & 31) * 4;
            uint2 raw = *(const uint2*)(Q + (size_t)(b * NN + n0 + t) * NQKV
                                          + (kvh * 4 + hh) * DD + d4);
            float2 f01 = __half22float2(*reinterpret_cast<__half2*>(&raw.x));
            float2 f23 = __half22float2(*reinterpret_cast<__half2*>(&raw.y));
            sm->qs[hh][t][d4 + 0] = f01.x; sm->qs[hh][t][d4 + 1] = f01.y;
            sm->qs[hh][t][d4 + 2] = f23.x; sm->qs[hh][t][d4 + 3] = f23.y;
        }
        {
            int t = tid >> 5, d4 = (tid & 31) * 4;
            uint2 raw = *(const uint2*)(K + (size_t)(b * NN + n0 + t) * NQKV
                                          + kvh * DD + d4);
            float2 f01 = __half22float2(*reinterpret_cast<__half2*>(&raw.x));
            float2 f23 = __half22float2(*reinterpret_cast<__half2*>(&raw.y));
            sm->ks[t][d4 + 0] = f01.x; sm->ks[t][d4 + 1] = f01.y;
            sm->ks[t][d4 + 2] = f23.x; sm->ks[t][d4 + 3] = f23.y;
            sm->gs[t][d4 + 0] = 1.f / (1.f + __expf(-f01.x));
            sm->gs[t][d4 + 1] = 1.f / (1.f + __expf(-f01.y));
            sm->gs[t][d4 + 2] = 1.f / (1.f + __expf(-f23.x));
            sm->gs[t][d4 + 3] = 1.f / (1.f + __expf(-f23.y));
        }
        if (tid < 64) {
            int t = tid >> 3, e = tid & 7;
            sm->vs[t][e] = __half2float(V[(size_t)(b * NN + n0 + t) * NQKV
                                          + kvh * DD + e0 + e]);
        }
        __syncthreads();

#pragma unroll
        for (int t = 0; t < 8; t++) {
            const float ve = sm->vs[t][w];
            const float g0 = sm->gs[t][lane],      g1 = sm->gs[t][lane + 32],
                        g2 = sm->gs[t][lane + 64], g3 = sm->gs[t][lane + 96];
            const float k0 = sm->ks[t][lane],      k1 = sm->ks[t][lane + 32],
                        k2 = sm->ks[t][lane + 64], k3 = sm->ks[t][lane + 96];
            s0 = s0 * g0 + k0 * ve;
            s1 = s1 * g1 + k1 * ve;
            s2 = s2 * g2 + k2 * ve;
            s3 = s3 * g3 + k3 * ve;
#pragma unroll
            for (int hh = 0; hh < 4; hh++) {
                float p = sm->qs[hh][t][lane]      * s0
                        + sm->qs[hh][t][lane + 32] * s1
                        + sm->qs[hh][t][lane + 64] * s2
                        + sm->qs[hh][t][lane + 96] * s3;
                p += __shfl_down_sync(0xffffffffu, p, 16);
                p += __shfl_down_sync(0xffffffffu, p, 8);
                p += __shfl_down_sync(0xffffffffu, p, 4);
                p += __shfl_down_sync(0xffffffffu, p, 2);
                p += __shfl_down_sync(0xffffffffu, p, 1);
                if (lane == 0) sm->os[t][hh][w] = p;
            }
        }
        __syncthreads();

        {
            int t = tid >> 5, hh = (tid >> 3) & 3, e = tid & 7;
            g_FLA[(size_t)(b * NN + n0 + t) * HIDD + (kvh * 4 + hh) * DD + e0 + e]
                = CSC * sm->os[t][hh][e];
        }
        __syncthreads();
    }
}

__global__ __launch_bounds__(256, 1)
void qkvfla_k(const __half* __restrict__ Xh, const __half* __restrict__ WTa,
              __half* __restrict__ QKV)
{
    extern __shared__ char smbuf[];
    const int bid = blockIdx.x;

    if (bid < NQK) {
        const int rto = bid / 24, ct = bid % 24;
        const int b = rto & 1, t = rto >> 1;
        const int rt = (b << 4) | t;
        const int rowA0 = rt * 128;
        const int colB0 = ct * 128;

        float acc[16][4];
        gemm_tile(smbuf, Xh, WTa, HIDD, rowA0, colB0, acc);

        const int tid  = threadIdx.x;
        const int lane = tid & 31;
        const int wid  = tid >> 5;
        const int wm   = wid >> 2;
        const int wn   = wid & 3;
        const int gr   = lane >> 2;
        const int gc   = lane & 3;

#pragma unroll
        for (int mt = 0; mt < 4; mt++) {
            int row = rowA0 + wm * 64 + mt * 16 + gr;
#pragma unroll
            for (int nt = 0; nt < 4; nt++) {
                int col = colB0 + wn * 32 + nt * 8 + gc * 2;
                const float* ac = acc[mt * 4 + nt];
                *(uint32_t*)(QKV + (size_t)row * NQKV + col) =
                    h2u(__floats2half2_rn(ac[0], ac[1]));
                *(uint32_t*)(QKV + (size_t)(row + 8) * NQKV + col) =
                    h2u(__floats2half2_rn(ac[2], ac[3]));
            }
        }
        __syncthreads();
        if (tid == 0) { __threadfence(); atomicAdd(&g_cntRT[rt], 1); }
    } else {
        fla_part(smbuf, QKV, QKV + DQ, QKV + DQ + DKV, bid - NQK);
    }
}

// ---------------- launch 2: flash + Wo -------------------------------------
// grid 1024: [0,512) flash (big-qi first); [512,1024) Wo (dep-spun on flash)
#define QPW 68
#define PPW2 36
#define NFLASH 512

struct FlashSmemH {
    uint32_t Qs[128 * QPW];
    uint32_t Kb[2][64 * QPW];
    uint32_t Vb[2][64 * QPW];
    uint32_t Ps[128 * PPW2];
    float red_m[4][128];
    float red_l[4][128];
    float sm_m[128];
    float sm_l[128];
};

__device__ __forceinline__ void flash_pfkv(FlashSmemH* sm, int s,
        const __half* __restrict__ K, const __half* __restrict__ V,
        int b, int j, int tid)
{
#pragma unroll
    for (int it = 0; it < 4; it++) {
        int id = tid + it * 256;
        int r = id >> 4, seg = id & 15;
        size_t goff = (size_t)(b * NN + j * 64 + r) * NQKV + seg * 8;
        cp16(&sm->Kb[s][r * QPW + seg * 4], K + goff);
        cp16(&sm->Vb[s][r * QPW + seg * 4], V + goff);
    }
}

__device__ void flash_part(char* smbuf, const __half* Q, const __half* K,
                           const __half* V, __half* AO, int bid2)
{
    FlashSmemH* sm = (FlashSmemH*)smbuf;

    const int bh = bid2 & 31;
    const int b  = bh >> 4, h = bh & 15;
    const int kvh = h >> 2;
    const int qi = 15 - (bid2 >> 5);

    const int tid  = threadIdx.x;
    const int lane = tid & 31;
    const int wid  = tid >> 5;
    const int wm   = wid >> 2;
    const int wn   = wid & 3;
    const int gr   = lane >> 2;
    const int gc   = lane & 3;

    const int nkv = 2 * qi + 2;
    const float LOG2E = 1.4426950408889634f;

    const __half* Kh = K + (size_t)kvh * DD;
    const __half* Vh = V + (size_t)kvh * DD;

    const int lrow  = lane & 15;
    const int lcolw = (lane >> 4) * 4;
    const uint32_t qfbase = (uint32_t)__cvta_generic_to_shared(sm->Qs)
                          + (uint32_t)(((wm * 64 + lrow) * QPW + lcolw) * 4);
    const uint32_t pfbase = (uint32_t)__cvta_generic_to_shared(sm->Ps)
                          + (uint32_t)(((wm * 64 + lrow) * PPW2 + lcolw) * 4);
    const uint32_t kfoff  = (uint32_t)(((wn * 16 + lrow) * QPW + lcolw) * 4);

#pragma unroll
    for (int it = 0; it < 8; it++) {
        int id = tid + it * 256;
        int r = id >> 4, seg = id & 15;
        cp16(&sm->Qs[r * QPW + seg * 4],
             Q + (size_t)(b * NN + qi * 128 + r) * NQKV + h * DD + seg * 8);
    }
    flash_pfkv(sm, 0, Kh, Vh, b, 0, tid);
    cp_commit();

    if (tid < 128) { sm->sm_m[tid] = -1e30f; sm->sm_l[tid] = 0.f; }

    float acc_o[16][4];
#pragma unroll
    for (int i = 0; i < 16; i++)
#pragma unroll
        for (int j = 0; j < 4; j++) acc_o[i][j] = 0.f;

    for (int j = 0; j < nkv; j++) {
        const int s = j & 1;
        __syncthreads();
        if (j + 1 < nkv)
            flash_pfkv(sm, s ^ 1, Kh, Vh, b, j + 1, tid);
        cp_commit();
        cp_wait<1>();
        __syncthreads();

        const uint32_t kst = (uint32_t)__cvta_generic_to_shared(sm->Kb[s]) + kfoff;

        float acc_s[8][4];
#pragma unroll
        for (int i = 0; i < 8; i++)
#pragma unroll
            for (int c = 0; c < 4; c++) acc_s[i][c] = 0.f;

#pragma unroll
        for (int ks = 0; ks < 8; ks++) {
            const int k2 = ks * 8;
            uint32_t a[4][4], bfr[2][2];
#pragma unroll
            for (int mt = 0; mt < 4; mt++)
                ldsm4(a[mt][0], a[mt][1], a[mt][2], a[mt][3],
                      qfbase + (uint32_t)((mt * 16 * QPW + k2) * 4));
            {
                uint32_t q0, q1, q2, q3;
                ldsm4(q0, q1, q2, q3, kst + (uint32_t)(k2 * 4));
                bfr[0][0] = q0; bfr[0][1] = q2;
                bfr[1][0] = q1; bfr[1][1] = q3;
            }
#pragma unroll
            for (int mt = 0; mt < 4; mt++)
#pragma unroll
                for (int nt = 0; nt < 2; nt++)
                    mma_h16(acc_s[mt * 2 + nt], a[mt], bfr[nt]);
        }

        if ((j + 1) * 64 - 1 > qi * 128) {
#pragma unroll
            for (int mt = 0; mt < 4; mt++)
#pragma unroll
                for (int nt = 0; nt < 2; nt++)
#pragma unroll
                    for (int c = 0; c < 4; c++) {
                        int rowg = qi * 128 + wm * 64 + mt * 16 + gr + (c >> 1) * 8;
                        int colg = j * 64 + wn * 16 + nt * 8 + 2 * gc + (c & 1);
                        if (colg > rowg) acc_s[mt * 2 + nt][c] = -1e30f;
                    }
        }

#pragma unroll
        for (int mt = 0; mt < 4; mt++)
#pragma unroll
            for (int hh = 0; hh < 2; hh++) {
                float rmax = fmaxf(fmaxf(acc_s[mt * 2 + 0][hh * 2], acc_s[mt * 2 + 0][hh * 2 + 1]),
                                   fmaxf(acc_s[mt * 2 + 1][hh * 2], acc_s[mt * 2 + 1][hh * 2 + 1]));
                rmax = fmaxf(rmax, __shfl_xor_sync(0xffffffffu, rmax, 1));
                rmax = fmaxf(rmax, __shfl_xor_sync(0xffffffffu, rmax, 2));
                if (gc == 0)
                    sm->red_m[wn][wm * 64 + mt * 16 + gr + hh * 8] = rmax;
            }
        __syncthreads();

#pragma unroll
        for (int mt = 0; mt < 4; mt++)
#pragma unroll
            for (int hh = 0; hh < 2; hh++) {
                int rl = wm * 64 + mt * 16 + gr + hh * 8;
                float m_old = sm->sm_m[rl];
                float m_new = fmaxf(fmaxf(sm->red_m[0][rl], sm->red_m[1][rl]),
                                    fmaxf(sm->red_m[2][rl], sm->red_m[3][rl]));
                m_new = fmaxf(m_old, m_new);
                float alpha = exp2f((m_old - m_new) * LOG2E);
#pragma unroll
                for (int nt = 0; nt < 4; nt++) {
                    acc_o[mt * 4 + nt][hh * 2]     *= alpha;
                    acc_o[mt * 4 + nt][hh * 2 + 1] *= alpha;
                }
                float psum = 0.f;
#pragma unroll
                for (int nt = 0; nt < 2; nt++) {
                    float p0 = exp2f((acc_s[mt * 2 + nt][hh * 2]     - m_new) * LOG2E);
                    float p1 = exp2f((acc_s[mt * 2 + nt][hh * 2 + 1] - m_new) * LOG2E);
                    psum += p0 + p1;
                    sm->Ps[rl * PPW2 + wn * 8 + nt * 4 + gc] = h2u(__floats2half2_rn(p0, p1));
                }
                psum += __shfl_xor_sync(0xffffffffu, psum, 1);
                psum += __shfl_xor_sync(0xffffffffu, psum, 2);
                if (gc == 0) sm->red_l[wn][rl] = psum;
            }
        __syncthreads();

        if (tid < 128) {
            int rl = tid;
            float m_old = sm->sm_m[rl];
            float m_new = fmaxf(fmaxf(sm->red_m[0][rl], sm->red_m[1][rl]),
                                fmaxf(sm->red_m[2][rl], sm->red_m[3][rl]));
            m_new = fmaxf(m_old, m_new);
            float alpha = exp2f((m_old - m_new) * LOG2E);
            sm->sm_l[rl] = sm->sm_l[rl] * alpha
                         + sm->red_l[0][rl] + sm->red_l[1][rl]
                         + sm->red_l[2][rl] + sm->red_l[3][rl];
            sm->sm_m[rl] = m_new;
        }

        uint32_t vbase = (uint32_t)__cvta_generic_to_shared(&sm->Vb[s][0]);
        const int mrow = lane >> 3, rr = lane & 7;
#pragma unroll
        for (int ks = 0; ks < 4; ks++) {
            const int k2 = ks * 8;
            uint32_t pa[4][4];
#pragma unroll
            for (int mt = 0; mt < 4; mt++)
                ldsm4(pa[mt][0], pa[mt][1], pa[mt][2], pa[mt][3],
                      pfbase + (uint32_t)((mt * 16 * PPW2 + k2) * 4));
#pragma unroll
            for (int np = 0; np < 2; np++) {
                int n0 = wn * 32 + np * 16;
                int token = ks * 16 + (mrow & 1) * 8 + rr;
                int d     = n0 + (mrow >> 1) * 8;
                uint32_t addr = vbase + (uint32_t)(token * QPW + (d >> 1)) * 4;
                uint32_t v0, v1, v2, v3;
                asm volatile(
                    "ldmatrix.sync.aligned.m8n8.x4.trans.shared.b16 {%0,%1,%2,%3}, [%4];"
                    : "=r"(v0), "=r"(v1), "=r"(v2), "=r"(v3) : "r"(addr));
                uint32_t b0[2] = {v0, v1}, b1[2] = {v2, v3};
#pragma unroll
                for (int mt = 0; mt < 4; mt++) {
                    mma_h16(acc_o[mt * 4 + np * 2 + 0], pa[mt], b0);
                    mma_h16(acc_o[mt * 4 + np * 2 + 1], pa[mt], b1);
                }
            }
        }
    }

    __syncthreads();

#pragma unroll
    for (int mt = 0; mt < 4; mt++)
#pragma unroll
        for (int hh = 0; hh < 2; hh++) {
            int rl = wm * 64 + mt * 16 + gr + hh * 8;
            float inv = 1.f / sm->sm_l[rl];
            int gq = qi * 128 + rl;
#pragma unroll
            for (int nt = 0; nt < 4; nt++) {
                int col = wn * 32 + nt * 8 + 2 * gc;
                *(uint32_t*)(AO + (size_t)(b * NN + gq) * DQ + h * DD + col) =
                    h2u(__floats2half2_rn(acc_o[mt * 4 + nt][hh * 2] * inv,
                                          acc_o[mt * 4 + nt][hh * 2 + 1] * inv));
            }
        }

    __syncthreads();
    if (tid == 0) { __threadfence(); atomicAdd(&g_cntFlash[b * 16 + qi], 1); }
}

// Wo tile: out = AO @ WTo^T + FLA (FLA already done in launch 1)
__device__ void wo_part(char* smbuf, const __half* __restrict__ Ag,
                        const __half* __restrict__ Bt,
                        float* __restrict__ outp, int bid3)
{
    const int rt = 31 - (bid3 >> 4);   // flash-completion order (big qi first)
    const int ct = bid3 & 15;
    const int b  = rt & 1, qi = rt >> 1;

    spin0(&g_cntFlash[b * 16 + qi], 16);

    const int rowA0 = (b * NN + qi * 128);
    const int colB0 = ct * 128;

    float acc[16][4];
    gemm_tile(smbuf, Ag, Bt, DQ, rowA0, colB0, acc);

    const int tid  = threadIdx.x;
    const int lane = tid & 31;
    const int wid  = tid >> 5;
    const int wm   = wid >> 2;
    const int wn   = wid & 3;
    const int gr   = lane >> 2;
    const int gc   = lane & 3;

#pragma unroll
    for (int mt = 0; mt < 4; mt++) {
        int row = rowA0 + wm * 64 + mt * 16 + gr;
#pragma unroll
        for (int nt = 0; nt < 4; nt++) {
            int col = colB0 + wn * 32 + nt * 8 + gc * 2;
            const float* ac = acc[mt * 4 + nt];
            const float* f0 = g_FLA + (size_t)row * HIDD + col;
            const float* f1 = g_FLA + (size_t)(row + 8) * HIDD + col;
            float2 rv0 = make_float2(ac[0] + f0[0], ac[1] + f0[1]);
            float2 rv1 = make_float2(ac[2] + f1[0], ac[3] + f1[1]);
            *(float2*)(outp + (size_t)row * HIDD + col) = rv0;
            *(float2*)(outp + (size_t)(row + 8) * HIDD + col) = rv1;
        }
    }
}

__global__ __launch_bounds__(256, 1)
void attn_wo_k(const __half* __restrict__ Q, const __half* __restrict__ K,
               const __half* __restrict__ V, __half* __restrict__ AO,
               const __half* __restrict__ WTo, float* __restrict__ out)
{
    extern __shared__ char smbuf[];
    const int bid = blockIdx.x;
    if (bid < NFLASH)
        flash_part(smbuf, Q, K, V, AO, bid);
    else
        wo_part(smbuf, AO, WTo, out, bid - NFLASH);
}

// ---------------- launch ---------------------------------------------------
extern "C" void kernel_launch(void* const* d_in, const int* in_sizes, int n_in,
                              void* d_out, int out_size)
{
    const float* hid = (const float*)d_in[0];
    const float* Wq  = (const float*)d_in[1];
    const float* Wk  = (const float*)d_in[2];
    const float* Wv  = (const float*)d_in[3];
    const float* Wo  = (const float*)d_in[4];
    float* outp = (float*)d_out;

    __half *Xh, *QKV, *AOh, *WTa, *WTo;
    cudaGetSymbolAddress((void**)&Xh,  g_Xh);
    cudaGetSymbolAddress((void**)&QKV, g_QKV);
    cudaGetSymbolAddress((void**)&AOh, g_AOh);
    cudaGetSymbolAddress((void**)&WTa, g_WTa);
    cudaGetSymbolAddress((void**)&WTo, g_WTo);

    cudaFuncSetAttribute((const void*)qkvfla_k, cudaFuncAttributeMaxDynamicSharedMemorySize, GEMM_SMEMH);
    cudaFuncSetAttribute((const void*)attn_wo_k, cudaFuncAttributeMaxDynamicSharedMemorySize,
                         (int)sizeof(FlashSmemH));

    const float scale = 0.08838834764831845f;

    // prepass: fp16 hidden + weight transposes + counter reset
    prep_k<<<PREP_BLOCKS, 256>>>(hid, Wq, Wk, Wv, Wo, Xh, WTa, WTo, scale);

    // launch 1: QKV projection + FLA (fla fills QKV's tail waves)
    qkvfla_k<<<NQK + NFLA, 256, GEMM_SMEMH>>>(Xh, WTa, QKV);

    // launch 2: flash + dependency-spun Wo
    attn_wo_k<<<NFLASH + 512, 256, sizeof(FlashSmemH)>>>(
        QKV, QKV + DQ, QKV + DQ + DKV, AOh, WTo, outp);
}

// round 16
// speedup vs baseline: 1.1066x; 1.1066x over previous
#include <cuda_runtime.h>
#include <cuda_fp16.h>
#include <math.h>
#include <stdint.h>

// Problem constants
#define BB   2
#define NN   2048
#define HIDD 2048
#define NH   16
#define NKV  4
#define DD   128
#define MQ   (BB*NN)        // 4096
#define DQ   (NH*DD)        // 2048
#define DKV  (NKV*DD)       // 512
#define NQKV (DQ + 2*DKV)   // 3072

// ---------------- device scratch ------------------------------------------
__device__ __half g_Xh  [(size_t)MQ * HIDD];
__device__ __half g_QKV [(size_t)MQ * NQKV];
__device__ __half g_AOh [(size_t)MQ * DQ];
__device__ __half g_WTa [(size_t)NQKV * HIDD];
__device__ __half g_WTo [(size_t)HIDD * DQ];
__device__ float  g_FLA [(size_t)MQ * HIDD];
__device__ int    g_cntFlash[32];   // per (b,qi) flash completion (16 each)
__device__ int    g_cntFla;         // fla blocks done (128)

// ---------------- helpers --------------------------------------------------
__device__ __forceinline__ void mma_h16(float* c, const uint32_t* a, const uint32_t* b) {
    asm volatile(
        "mma.sync.aligned.m16n8k16.row.col.f32.f16.f16.f32 "
        "{%0,%1,%2,%3}, {%4,%5,%6,%7}, {%8,%9}, {%0,%1,%2,%3};\n"
        : "+f"(c[0]), "+f"(c[1]), "+f"(c[2]), "+f"(c[3])
        : "r"(a[0]), "r"(a[1]), "r"(a[2]), "r"(a[3]),
          "r"(b[0]), "r"(b[1]));
}
__device__ __forceinline__ void ldsm4(uint32_t& r0, uint32_t& r1, uint32_t& r2,
                                      uint32_t& r3, uint32_t addr) {
    asm volatile("ldmatrix.sync.aligned.m8n8.x4.shared.b16 {%0,%1,%2,%3}, [%4];"
                 : "=r"(r0), "=r"(r1), "=r"(r2), "=r"(r3) : "r"(addr));
}
__device__ __forceinline__ void cp16(void* smem, const void* gmem) {
    uint32_t s = (uint32_t)__cvta_generic_to_shared(smem);
    asm volatile("cp.async.cg.shared.global [%0], [%1], 16;\n" :: "r"(s), "l"(gmem));
}
__device__ __forceinline__ void cp_commit() { asm volatile("cp.async.commit_group;\n"); }
template<int N8>
__device__ __forceinline__ void cp_wait() { asm volatile("cp.async.wait_group %0;\n" :: "n"(N8)); }
__device__ __forceinline__ uint32_t h2u(__half2 h) { return *reinterpret_cast<uint32_t*>(&h); }

// ---------------- merged prepass kernel ------------------------------------
#define PB_CONV 8192
#define PB_WQ   4096
#define PB_WKV  1024
#define PB_WO   4096
#define PREP_BLOCKS (PB_CONV + PB_WQ + 2*PB_WKV + PB_WO + 1)

__device__ __forceinline__ void transh_dev(const float* __restrict__ W,
        __half* __restrict__ WT, int K, int N, float alpha, int bx, int by,
        float (*t)[33])
{
    int k0 = by * 32, n0 = bx * 32;
    int tx = threadIdx.x & 31, ty = threadIdx.x >> 5;
#pragma unroll
    for (int i = 0; i < 4; i++)
        t[ty + 8 * i][tx] = W[(long)(k0 + ty + 8 * i) * N + n0 + tx];
    __syncthreads();
#pragma unroll
    for (int i = 0; i < 4; i++)
        WT[(long)(n0 + ty + 8 * i) * K + k0 + tx] = __float2half_rn(alpha * t[tx][ty + 8 * i]);
}

__global__ __launch_bounds__(256)
void prep_k(const float* __restrict__ hid,
            const float* __restrict__ Wq, const float* __restrict__ Wk,
            const float* __restrict__ Wv, const float* __restrict__ Wo,
            __half* __restrict__ Xh, __half* __restrict__ WTa,
            __half* __restrict__ WTo, float scale)
{
    __shared__ float t[32][33];
    const int bid = blockIdx.x;

    if (bid < PB_CONV) {
        int i = bid * 256 + threadIdx.x;
        float4 v = ((const float4*)hid)[i];
        uint2 o;
        o.x = h2u(__floats2half2_rn(v.x, v.y));
        o.y = h2u(__floats2half2_rn(v.z, v.w));
        ((uint2*)Xh)[i] = o;
    } else if (bid < PB_CONV + PB_WQ) {
        int tbid = bid - PB_CONV;
        transh_dev(Wq, WTa, HIDD, DQ, scale, tbid & 63, tbid >> 6, t);
    } else if (bid < PB_CONV + PB_WQ + PB_WKV) {
        int tbid = bid - PB_CONV - PB_WQ;
        transh_dev(Wk, WTa + (size_t)DQ * HIDD, HIDD, DKV, 1.f,
                   tbid & 15, tbid >> 4, t);
    } else if (bid < PB_CONV + PB_WQ + 2 * PB_WKV) {
        int tbid = bid - PB_CONV - PB_WQ - PB_WKV;
        transh_dev(Wv, WTa + (size_t)(DQ + DKV) * HIDD, HIDD, DKV, 1.f,
                   tbid & 15, tbid >> 4, t);
    } else if (bid < PB_CONV + PB_WQ + 2 * PB_WKV + PB_WO) {
        int tbid = bid - PB_CONV - PB_WQ - 2 * PB_WKV;
        transh_dev(Wo, WTo, DQ, HIDD, 1.f, tbid & 63, tbid >> 6, t);
    } else {
        if (threadIdx.x < 32) g_cntFlash[threadIdx.x] = 0;
        if (threadIdx.x == 32) g_cntFla = 0;
    }
}

// ---------------- fp16 GEMM (standalone, QKV projection) -------------------
#define HP    20
#define HSTGW (128*HP)
#define GEMM_SMEMH (4*2*HSTGW*4)

__global__ __launch_bounds__(256)
void gemm_h(const __half* __restrict__ Ag, const __half* __restrict__ Bt,
            __half* __restrict__ Cg, int Kdim, int N, float alpha)
{
    extern __shared__ uint32_t smw[];
    uint32_t* Asb = smw;
    uint32_t* Bsb = smw + 4 * HSTGW;
    const uint32_t abase = (uint32_t)__cvta_generic_to_shared(Asb);
    const uint32_t bbase = (uint32_t)__cvta_generic_to_shared(Bsb);

    const int bx = blockIdx.x, by = blockIdx.y;
    const int tid  = threadIdx.x;
    const int lane = tid & 31;
    const int wid  = tid >> 5;
    const int wm   = wid >> 2;
    const int wn   = wid & 3;
    const int gr   = lane >> 2;
    const int gc   = lane & 3;

    const int rowA0 = by * 128;
    const int colB0 = bx * 128;
    const int niter = Kdim / 32;

    const int lrow  = lane & 15;
    const int lcolw = (lane >> 4) * 4;
    const uint32_t aoff = (uint32_t)(((wm * 64 + lrow) * HP + lcolw) * 4);
    const uint32_t boff = (uint32_t)(((wn * 32 + lrow) * HP + lcolw) * 4);

    const int r0 = tid >> 2,         s0 = (tid & 3);
    const int r1 = (tid + 256) >> 2, s1 = ((tid + 256) & 3);

#pragma unroll
    for (int s = 0; s < 3; s++) {
        int k0 = s * 32;
        uint32_t* As = Asb + s * HSTGW;
        uint32_t* Bs = Bsb + s * HSTGW;
        cp16(&As[r0 * HP + s0 * 4], Ag + (size_t)(rowA0 + r0) * Kdim + k0 + s0 * 8);
        cp16(&As[r1 * HP + s1 * 4], Ag + (size_t)(rowA0 + r1) * Kdim + k0 + s1 * 8);
        cp16(&Bs[r0 * HP + s0 * 4], Bt + (size_t)(colB0 + r0) * Kdim + k0 + s0 * 8);
        cp16(&Bs[r1 * HP + s1 * 4], Bt + (size_t)(colB0 + r1) * Kdim + k0 + s1 * 8);
        cp_commit();
    }

    float acc[16][4];
#pragma unroll
    for (int i = 0; i < 16; i++)
#pragma unroll
        for (int j = 0; j < 4; j++) acc[i][j] = 0.f;

    for (int i = 0; i < niter; i++) {
        cp_wait<2>();
        __syncthreads();
        if (i + 3 < niter) {
            int st = (i + 3) & 3;
            int k0 = (i + 3) * 32;
            uint32_t* As = Asb + st * HSTGW;
            uint32_t* Bs = Bsb + st * HSTGW;
            cp16(&As[r0 * HP + s0 * 4], Ag + (size_t)(rowA0 + r0) * Kdim + k0 + s0 * 8);
            cp16(&As[r1 * HP + s1 * 4], Ag + (size_t)(rowA0 + r1) * Kdim + k0 + s1 * 8);
            cp16(&Bs[r0 * HP + s0 * 4], Bt + (size_t)(colB0 + r0) * Kdim + k0 + s0 * 8);
            cp16(&Bs[r1 * HP + s1 * 4], Bt + (size_t)(colB0 + r1) * Kdim + k0 + s1 * 8);
        }
        cp_commit();

        const uint32_t ast = abase + (uint32_t)((i & 3) * HSTGW * 4);
        const uint32_t bst = bbase + (uint32_t)((i & 3) * HSTGW * 4);

#pragma unroll
        for (int ks = 0; ks < 2; ks++) {
            const int k2 = ks * 8;
            uint32_t a[4][4], bf[4][2];
#pragma unroll
            for (int mt = 0; mt < 4; mt++)
                ldsm4(a[mt][0], a[mt][1], a[mt][2], a[mt][3],
                      ast + aoff + (uint32_t)((mt * 16 * HP + k2) * 4));
#pragma unroll
            for (int p = 0; p < 2; p++) {
                uint32_t q0, q1, q2, q3;
                ldsm4(q0, q1, q2, q3, bst + boff + (uint32_t)((p * 16 * HP + k2) * 4));
                bf[2 * p][0] = q0;     bf[2 * p][1] = q2;
                bf[2 * p + 1][0] = q1; bf[2 * p + 1][1] = q3;
            }
#pragma unroll
            for (int mt = 0; mt < 4; mt++)
#pragma unroll
                for (int nt = 0; nt < 4; nt++)
                    mma_h16(acc[mt * 4 + nt], a[mt], bf[nt]);
        }
    }

#pragma unroll
    for (int mt = 0; mt < 4; mt++) {
        int row = rowA0 + wm * 64 + mt * 16 + gr;
#pragma unroll
        for (int nt = 0; nt < 4; nt++) {
            int col = colB0 + wn * 32 + nt * 8 + gc * 2;
            const float* ac = acc[mt * 4 + nt];
            *(uint32_t*)(Cg + (size_t)row * N + col) =
                h2u(__floats2half2_rn(ac[0], ac[1]));
            *(uint32_t*)(Cg + (size_t)(row + 8) * N + col) =
                h2u(__floats2half2_rn(ac[2], ac[3]));
        }
    }
}

// ---------------- fused attn + Wo kernel ----------------------------------
// grid 1152: [0,128) FLA; [128,640) flash (big-qi first); [640,1152) Wo
#define QPW 68
#define PPW2 36
#define NFLA 128
#define NFLASH 512

struct FlashSmemH {
    uint32_t Qs[128 * QPW];
    uint32_t Kb[2][64 * QPW];
    uint32_t Vb[2][64 * QPW];
    uint32_t Ps[128 * PPW2];
    float red_m[4][128];
    float red_l[4][128];
};

struct FlaSmem {
    float ks[8][128];
    float gs[8][128];
    float qs[4][8][128];
    float vs[8][8];
    float os[8][4][8];
};

__device__ __forceinline__ void flash_pfkv(FlashSmemH* sm, int s,
        const __half* __restrict__ K, const __half* __restrict__ V,
        int b, int j, int tid)
{
#pragma unroll
    for (int it = 0; it < 4; it++) {
        int id = tid + it * 256;
        int r = id >> 4, seg = id & 15;
        size_t goff = (size_t)(b * NN + j * 64 + r) * NQKV + seg * 8;
        cp16(&sm->Kb[s][r * QPW + seg * 4], K + goff);
        cp16(&sm->Vb[s][r * QPW + seg * 4], V + goff);
    }
}

__device__ void fla_part(char* smbuf, const __half* Q, const __half* K,
                         const __half* V, int bid)
{
    FlaSmem* sm = (FlaSmem*)smbuf;
    const int et  = bid & 15;
    const int kvh = (bid >> 4) & 3;
    const int b   = bid >> 6;
    const int e0  = et * 8;
    const int tid = threadIdx.x;
    const int lane = tid & 31;
    const int w    = tid >> 5;

    float s0 = 0.f, s1 = 0.f, s2 = 0.f, s3 = 0.f;
    const float CSC = 0.01f;

    for (int c = 0; c < 256; c++) {
        const int n0 = c * 8;
#pragma unroll
        for (int i = 0; i < 4; i++) {
            int id = tid + i * 256;
            int hh = id >> 8, t = (id >> 5) & 7, d4 = (id & 31) * 4;
            uint2 raw = *(const uint2*)(Q + (size_t)(b * NN + n0 + t) * NQKV
                                          + (kvh * 4 + hh) * DD + d4);
            float2 f01 = __half22float2(*reinterpret_cast<__half2*>(&raw.x));
            float2 f23 = __half22float2(*reinterpret_cast<__half2*>(&raw.y));
            sm->qs[hh][t][d4 + 0] = f01.x; sm->qs[hh][t][d4 + 1] = f01.y;
            sm->qs[hh][t][d4 + 2] = f23.x; sm->qs[hh][t][d4 + 3] = f23.y;
        }
        {
            int t = tid >> 5, d4 = (tid & 31) * 4;
            uint2 raw = *(const uint2*)(K + (size_t)(b * NN + n0 + t) * NQKV
                                          + kvh * DD + d4);
            float2 f01 = __half22float2(*reinterpret_cast<__half2*>(&raw.x));
            float2 f23 = __half22float2(*reinterpret_cast<__half2*>(&raw.y));
            sm->ks[t][d4 + 0] = f01.x; sm->ks[t][d4 + 1] = f01.y;
            sm->ks[t][d4 + 2] = f23.x; sm->ks[t][d4 + 3] = f23.y;
            sm->gs[t][d4 + 0] = 1.f / (1.f + __expf(-f01.x));
            sm->gs[t][d4 + 1] = 1.f / (1.f + __expf(-f01.y));
            sm->gs[t][d4 + 2] = 1.f / (1.f + __expf(-f23.x));
            sm->gs[t][d4 + 3] = 1.f / (1.f + __expf(-f23.y));
        }
        if (tid < 64) {
            int t = tid >> 3, e = tid & 7;
            sm->vs[t][e] = __half2float(V[(size_t)(b * NN + n0 + t) * NQKV
                                          + kvh * DD + e0 + e]);
        }
        __syncthreads();

#pragma unroll
        for (int t = 0; t < 8; t++) {
            const float ve = sm->vs[t][w];
            const float g0 = sm->gs[t][lane],      g1 = sm->gs[t][lane + 32],
                        g2 = sm->gs[t][lane + 64], g3 = sm->gs[t][lane + 96];
            const float k0 = sm->ks[t][lane],      k1 = sm->ks[t][lane + 32],
                        k2 = sm->ks[t][lane + 64], k3 = sm->ks[t][lane + 96];
            s0 = s0 * g0 + k0 * ve;
            s1 = s1 * g1 + k1 * ve;
            s2 = s2 * g2 + k2 * ve;
            s3 = s3 * g3 + k3 * ve;
#pragma unroll
            for (int hh = 0; hh < 4; hh++) {
                float p = sm->qs[hh][t][lane]      * s0
                        + sm->qs[hh][t][lane + 32] * s1
                        + sm->qs[hh][t][lane + 64] * s2
                        + sm->qs[hh][t][lane + 96] * s3;
                p += __shfl_down_sync(0xffffffffu, p, 16);
                p += __shfl_down_sync(0xffffffffu, p, 8);
                p += __shfl_down_sync(0xffffffffu, p, 4);
                p += __shfl_down_sync(0xffffffffu, p, 2);
                p += __shfl_down_sync(0xffffffffu, p, 1);
                if (lane == 0) sm->os[t][hh][w] = p;
            }
        }
        __syncthreads();

        {
            int t = tid >> 5, hh = (tid >> 3) & 3, e = tid & 7;
            g_FLA[(size_t)(b * NN + n0 + t) * HIDD + (kvh * 4 + hh) * DD + e0 + e]
                = CSC * sm->os[t][hh][e];
        }
        __syncthreads();
    }

    if (tid == 0) { __threadfence(); atomicAdd(&g_cntFla, 1); }
}

__device__ void flash_part(char* smbuf, const __half* Q, const __half* K,
                           const __half* V, __half* AO, int bid2)
{
    FlashSmemH* sm = (FlashSmemH*)smbuf;

    const int bh = bid2 & 31;
    const int b  = bh >> 4, h = bh & 15;
    const int kvh = h >> 2;
    const int qi = 15 - (bid2 >> 5);

    const int tid  = threadIdx.x;
    const int lane = tid & 31;
    const int wid  = tid >> 5;
    const int wm   = wid >> 2;
    const int wn   = wid & 3;
    const int gr   = lane >> 2;
    const int gc   = lane & 3;

    const int nkv = 2 * qi + 2;
    const float LOG2E = 1.4426950408889634f;

    const __half* Kh = K + (size_t)kvh * DD;
    const __half* Vh = V + (size_t)kvh * DD;

    const int lrow  = lane & 15;
    const int lcolw = (lane >> 4) * 4;
    const uint32_t qfbase = (uint32_t)__cvta_generic_to_shared(sm->Qs)
                          + (uint32_t)(((wm * 64 + lrow) * QPW + lcolw) * 4);
    const uint32_t pfbase = (uint32_t)__cvta_generic_to_shared(sm->Ps)
                          + (uint32_t)(((wm * 64 + lrow) * PPW2 + lcolw) * 4);
    const uint32_t kfoff  = (uint32_t)(((wn * 16 + lrow) * QPW + lcolw) * 4);

#pragma unroll
    for (int it = 0; it < 8; it++) {
        int id = tid + it * 256;
        int r = id >> 4, seg = id & 15;
        cp16(&sm->Qs[r * QPW + seg * 4],
             Q + (size_t)(b * NN + qi * 128 + r) * NQKV + h * DD + seg * 8);
    }
    flash_pfkv(sm, 0, Kh, Vh, b, 0, tid);
    cp_commit();

    // register-resident softmax stats (per thread: rows mt*16+gr+hh*8 + wm*64)
    float mreg[4][2], lreg[4][2];
#pragma unroll
    for (int mt = 0; mt < 4; mt++)
#pragma unroll
        for (int hh = 0; hh < 2; hh++) { mreg[mt][hh] = -1e30f; lreg[mt][hh] = 0.f; }

    float acc_o[16][4];
#pragma unroll
    for (int i = 0; i < 16; i++)
#pragma unroll
        for (int j = 0; j < 4; j++) acc_o[i][j] = 0.f;

    for (int j = 0; j < nkv; j++) {
        const int s = j & 1;
        __syncthreads();
        if (j + 1 < nkv)
            flash_pfkv(sm, s ^ 1, Kh, Vh, b, j + 1, tid);
        cp_commit();
        cp_wait<1>();
        __syncthreads();

        const uint32_t kst = (uint32_t)__cvta_generic_to_shared(sm->Kb[s]) + kfoff;

        float acc_s[8][4];
#pragma unroll
        for (int i = 0; i < 8; i++)
#pragma unroll
            for (int c = 0; c < 4; c++) acc_s[i][c] = 0.f;

#pragma unroll
        for (int ks = 0; ks < 8; ks++) {
            const int k2 = ks * 8;
            uint32_t a[4][4], bfr[2][2];
#pragma unroll
            for (int mt = 0; mt < 4; mt++)
                ldsm4(a[mt][0], a[mt][1], a[mt][2], a[mt][3],
                      qfbase + (uint32_t)((mt * 16 * QPW + k2) * 4));
            {
                uint32_t q0, q1, q2, q3;
                ldsm4(q0, q1, q2, q3, kst + (uint32_t)(k2 * 4));
                bfr[0][0] = q0; bfr[0][1] = q2;
                bfr[1][0] = q1; bfr[1][1] = q3;
            }
#pragma unroll
            for (int mt = 0; mt < 4; mt++)
#pragma unroll
                for (int nt = 0; nt < 2; nt++)
                    mma_h16(acc_s[mt * 2 + nt], a[mt], bfr[nt]);
        }

        if ((j + 1) * 64 - 1 > qi * 128) {
#pragma unroll
            for (int mt = 0; mt < 4; mt++)
#pragma unroll
                for (int nt = 0; nt < 2; nt++)
#pragma unroll
                    for (int c = 0; c < 4; c++) {
                        int rowg = qi * 128 + wm * 64 + mt * 16 + gr + (c >> 1) * 8;
                        int colg = j * 64 + wn * 16 + nt * 8 + 2 * gc + (c & 1);
                        if (colg > rowg) acc_s[mt * 2 + nt][c] = -1e30f;
                    }
        }

        // row-max partials
#pragma unroll
        for (int mt = 0; mt < 4; mt++)
#pragma unroll
            for (int hh = 0; hh < 2; hh++) {
                float rmax = fmaxf(fmaxf(acc_s[mt * 2 + 0][hh * 2], acc_s[mt * 2 + 0][hh * 2 + 1]),
                                   fmaxf(acc_s[mt * 2 + 1][hh * 2], acc_s[mt * 2 + 1][hh * 2 + 1]));
                rmax = fmaxf(rmax, __shfl_xor_sync(0xffffffffu, rmax, 1));
                rmax = fmaxf(rmax, __shfl_xor_sync(0xffffffffu, rmax, 2));
                if (gc == 0)
                    sm->red_m[wn][wm * 64 + mt * 16 + gr + hh * 8] = rmax;
            }
        __syncthreads();

        // softmax: per-thread stats from shared partials (no sm_m/sm_l)
        float al[4][2];
#pragma unroll
        for (int mt = 0; mt < 4; mt++)
#pragma unroll
            for (int hh = 0; hh < 2; hh++) {
                int rl = wm * 64 + mt * 16 + gr + hh * 8;
                float m_old = mreg[mt][hh];
                float m_new = fmaxf(fmaxf(sm->red_m[0][rl], sm->red_m[1][rl]),
                                    fmaxf(sm->red_m[2][rl], sm->red_m[3][rl]));
                m_new = fmaxf(m_old, m_new);
                float alpha = exp2f((m_old - m_new) * LOG2E);
                al[mt][hh] = alpha;
                mreg[mt][hh] = m_new;
#pragma unroll
                for (int nt = 0; nt < 4; nt++) {
                    acc_o[mt * 4 + nt][hh * 2]     *= alpha;
                    acc_o[mt * 4 + nt][hh * 2 + 1] *= alpha;
                }
                float psum = 0.f;
#pragma unroll
                for (int nt = 0; nt < 2; nt++) {
                    float p0 = exp2f((acc_s[mt * 2 + nt][hh * 2]     - m_new) * LOG2E);
                    float p1 = exp2f((acc_s[mt * 2 + nt][hh * 2 + 1] - m_new) * LOG2E);
                    psum += p0 + p1;
                    sm->Ps[rl * PPW2 + wn * 8 + nt * 4 + gc] = h2u(__floats2half2_rn(p0, p1));
                }
                psum += __shfl_xor_sync(0xffffffffu, psum, 1);
                psum += __shfl_xor_sync(0xffffffffu, psum, 2);
                if (gc == 0) sm->red_l[wn][rl] = psum;
            }
        __syncthreads();

        // l update from shared partials (register-resident)
#pragma unroll
        for (int mt = 0; mt < 4; mt++)
#pragma unroll
            for (int hh = 0; hh < 2; hh++) {
                int rl = wm * 64 + mt * 16 + gr + hh * 8;
                lreg[mt][hh] = lreg[mt][hh] * al[mt][hh]
                             + sm->red_l[0][rl] + sm->red_l[1][rl]
                             + sm->red_l[2][rl] + sm->red_l[3][rl];
            }

        // PV: acc_o += P @ V
        uint32_t vbase = (uint32_t)__cvta_generic_to_shared(&sm->Vb[s][0]);
        const int mrow = lane >> 3, rr = lane & 7;
#pragma unroll
        for (int ks = 0; ks < 4; ks++) {
            const int k2 = ks * 8;
            uint32_t pa[4][4];
#pragma unroll
            for (int mt = 0; mt < 4; mt++)
                ldsm4(pa[mt][0], pa[mt][1], pa[mt][2], pa[mt][3],
                      pfbase + (uint32_t)((mt * 16 * PPW2 + k2) * 4));
#pragma unroll
            for (int np = 0; np < 2; np++) {
                int n0 = wn * 32 + np * 16;
                int token = ks * 16 + (mrow & 1) * 8 + rr;
                int d     = n0 + (mrow >> 1) * 8;
                uint32_t addr = vbase + (uint32_t)(token * QPW + (d >> 1)) * 4;
                uint32_t v0, v1, v2, v3;
                asm volatile(
                    "ldmatrix.sync.aligned.m8n8.x4.trans.shared.b16 {%0,%1,%2,%3}, [%4];"
                    : "=r"(v0), "=r"(v1), "=r"(v2), "=r"(v3) : "r"(addr));
                uint32_t b0[2] = {v0, v1}, b1[2] = {v2, v3};
#pragma unroll
                for (int mt = 0; mt < 4; mt++) {
                    mma_h16(acc_o[mt * 4 + np * 2 + 0], pa[mt], b0);
                    mma_h16(acc_o[mt * 4 + np * 2 + 1], pa[mt], b1);
                }
            }
        }
    }

    // epilogue: AO = fp16(acc_o / l)  (stats are register-resident)
#pragma unroll
    for (int mt = 0; mt < 4; mt++)
#pragma unroll
        for (int hh = 0; hh < 2; hh++) {
            int rl = wm * 64 + mt * 16 + gr + hh * 8;
            float inv = 1.f / lreg[mt][hh];
            int gq = qi * 128 + rl;
#pragma unroll
            for (int nt = 0; nt < 4; nt++) {
                int col = wn * 32 + nt * 8 + 2 * gc;
                *(uint32_t*)(AO + (size_t)(b * NN + gq) * DQ + h * DD + col) =
                    h2u(__floats2half2_rn(acc_o[mt * 4 + nt][hh * 2] * inv,
                                          acc_o[mt * 4 + nt][hh * 2 + 1] * inv));
            }
        }

    __syncthreads();
    if (tid == 0) { __threadfence(); atomicAdd(&g_cntFlash[b * 16 + qi], 1); }
}

// Wo tile GEMM with spin dependencies: out = AO @ WTo^T + FLA
__device__ void wo_part(char* smbuf, const __half* __restrict__ Ag,
                        const __half* __restrict__ Bt,
                        float* __restrict__ outp, int bid3)
{
    const int rt = bid3 >> 4;
    const int ct = bid3 & 15;
    const int b  = rt & 1, qi = rt >> 1;

    const int tid  = threadIdx.x;

    if (tid == 0) {
        while (atomicAdd(&g_cntFlash[b * 16 + qi], 0) < 16) __nanosleep(256);
    }
    __syncthreads();
    __threadfence();

    uint32_t* smw = (uint32_t*)smbuf;
    uint32_t* Asb = smw;
    uint32_t* Bsb = smw + 4 * HSTGW;
    const uint32_t abase = (uint32_t)__cvta_generic_to_shared(Asb);
    const uint32_t bbase = (uint32_t)__cvta_generic_to_shared(Bsb);

    const int lane = tid & 31;
    const int wid  = tid >> 5;
    const int wm   = wid >> 2;
    const int wn   = wid & 3;
    const int gr   = lane >> 2;
    const int gc   = lane & 3;

    const int Kdim = DQ;
    const int rowA0 = (b * NN + qi * 128);
    const int colB0 = ct * 128;
    const int niter = Kdim / 32;

    const int lrow  = lane & 15;
    const int lcolw = (lane >> 4) * 4;
    const uint32_t aoff = (uint32_t)(((wm * 64 + lrow) * HP + lcolw) * 4);
    const uint32_t boff = (uint32_t)(((wn * 32 + lrow) * HP + lcolw) * 4);

    const int r0 = tid >> 2,         s0 = (tid & 3);
    const int r1 = (tid + 256) >> 2, s1 = ((tid + 256) & 3);

#pragma unroll
    for (int s = 0; s < 3; s++) {
        int k0 = s * 32;
        uint32_t* As = Asb + s * HSTGW;
        uint32_t* Bs = Bsb + s * HSTGW;
        cp16(&As[r0 * HP + s0 * 4], Ag + (size_t)(rowA0 + r0) * Kdim + k0 + s0 * 8);
        cp16(&As[r1 * HP + s1 * 4], Ag + (size_t)(rowA0 + r1) * Kdim + k0 + s1 * 8);
        cp16(&Bs[r0 * HP + s0 * 4], Bt + (size_t)(colB0 + r0) * Kdim + k0 + s0 * 8);
        cp16(&Bs[r1 * HP + s1 * 4], Bt + (size_t)(colB0 + r1) * Kdim + k0 + s1 * 8);
        cp_commit();
    }

    float acc[16][4];
#pragma unroll
    for (int i = 0; i < 16; i++)
#pragma unroll
        for (int j = 0; j < 4; j++) acc[i][j] = 0.f;

    for (int i = 0; i < niter; i++) {
        cp_wait<2>();
        __syncthreads();
        if (i + 3 < niter) {
            int st = (i + 3) & 3;
            int k0 = (i + 3) * 32;
            uint32_t* As = Asb + st * HSTGW;
            uint32_t* Bs = Bsb + st * HSTGW;
            cp16(&As[r0 * HP + s0 * 4], Ag + (size_t)(rowA0 + r0) * Kdim + k0 + s0 * 8);
            cp16(&As[r1 * HP + s1 * 4], Ag + (size_t)(rowA0 + r1) * Kdim + k0 + s1 * 8);
            cp16(&Bs[r0 * HP + s0 * 4], Bt + (size_t)(colB0 + r0) * Kdim + k0 + s0 * 8);
            cp16(&Bs[r1 * HP + s1 * 4], Bt + (size_t)(colB0 + r1) * Kdim + k0 + s1 * 8);
        }
        cp_commit();

        const uint32_t ast = abase + (uint32_t)((i & 3) * HSTGW * 4);
        const uint32_t bst = bbase + (uint32_t)((i & 3) * HSTGW * 4);

#pragma unroll
        for (int ks = 0; ks < 2; ks++) {
            const int k2 = ks * 8;
            uint32_t a[4][4], bf[4][2];
#pragma unroll
            for (int mt = 0; mt < 4; mt++)
                ldsm4(a[mt][0], a[mt][1], a[mt][2], a[mt][3],
                      ast + aoff + (uint32_t)((mt * 16 * HP + k2) * 4));
#pragma unroll
            for (int p = 0; p < 2; p++) {
                uint32_t q0, q1, q2, q3;
                ldsm4(q0, q1, q2, q3, bst + boff + (uint32_t)((p * 16 * HP + k2) * 4));
                bf[2 * p][0] = q0;     bf[2 * p][1] = q2;
                bf[2 * p + 1][0] = q1; bf[2 * p + 1][1] = q3;
            }
#pragma unroll
            for (int mt = 0; mt < 4; mt++)
#pragma unroll
                for (int nt = 0; nt < 4; nt++)
                    mma_h16(acc[mt * 4 + nt], a[mt], bf[nt]);
        }
    }

    if (tid == 0) {
        while (atomicAdd(&g_cntFla, 0) < NFLA) __nanosleep(256);
    }
    __syncthreads();
    __threadfence();

#pragma unroll
    for (int mt = 0; mt < 4; mt++) {
        int row = rowA0 + wm * 64 + mt * 16 + gr;
#pragma unroll
        for (int nt = 0; nt < 4; nt++) {
            int col = colB0 + wn * 32 + nt * 8 + gc * 2;
            const float* ac = acc[mt * 4 + nt];
            const float* f0 = g_FLA + (size_t)row * HIDD + col;
            const float* f1 = g_FLA + (size_t)(row + 8) * HIDD + col;
            float2 rv0 = make_float2(ac[0] + f0[0], ac[1] + f0[1]);
            float2 rv1 = make_float2(ac[2] + f1[0], ac[3] + f1[1]);
            *(float2*)(outp + (size_t)row * HIDD + col) = rv0;
            *(float2*)(outp + (size_t)(row + 8) * HIDD + col) = rv1;
        }
    }
}

__global__ __launch_bounds__(256, 1)
void fused_all_k(const __half* __restrict__ Q, const __half* __restrict__ K,
                 const __half* __restrict__ V, __half* __restrict__ AO,
                 const __half* __restrict__ WTo, float* __restrict__ out)
{
    extern __shared__ char smbuf[];
    const int bid = blockIdx.x;
    if (bid < NFLA)
        fla_part(smbuf, Q, K, V, bid);
    else if (bid < NFLA + NFLASH)
        flash_part(smbuf, Q, K, V, AO, bid - NFLA);
    else
        wo_part(smbuf, AO, WTo, out, bid - NFLA - NFLASH);
}

// ---------------- launch ---------------------------------------------------
extern "C" void kernel_launch(void* const* d_in, const int* in_sizes, int n_in,
                              void* d_out, int out_size)
{
    const float* hid = (const float*)d_in[0];
    const float* Wq  = (const float*)d_in[1];
    const float* Wk  = (const float*)d_in[2];
    const float* Wv  = (const float*)d_in[3];
    const float* Wo  = (const float*)d_in[4];
    float* outp = (float*)d_out;

    __half *Xh, *QKV, *AOh, *WTa, *WTo;
    cudaGetSymbolAddress((void**)&Xh,  g_Xh);
    cudaGetSymbolAddress((void**)&QKV, g_QKV);
    cudaGetSymbolAddress((void**)&AOh, g_AOh);
    cudaGetSymbolAddress((void**)&WTa, g_WTa);
    cudaGetSymbolAddress((void**)&WTo, g_WTo);

    cudaFuncSetAttribute((const void*)gemm_h, cudaFuncAttributeMaxDynamicSharedMemorySize, GEMM_SMEMH);
    cudaFuncSetAttribute((const void*)fused_all_k, cudaFuncAttributeMaxDynamicSharedMemorySize,
                         (int)sizeof(FlashSmemH));

    const float scale = 0.08838834764831845f;

    // single merged prepass: fp16 hidden + 4 weight transposes + counter reset
    prep_k<<<PREP_BLOCKS, 256>>>(hid, Wq, Wk, Wv, Wo, Xh, WTa, WTo, scale);

    // fused QKV projection
    gemm_h<<<dim3(NQKV / 128, MQ / 128), 256, GEMM_SMEMH>>>(
        Xh, WTa, QKV, HIDD, NQKV, 1.f);

    const __half* Qh = QKV;
    const __half* Kh = QKV + DQ;
    const __half* Vh = QKV + DQ + DKV;

    // FLA + flash + dependency-spun Wo, one launch
    fused_all_k<<<NFLA + NFLASH + 512, 256, sizeof(FlashSmemH)>>>(
        Qh, Kh, Vh, AOh, WTo, outp);
}

// round 17
// speedup vs baseline: 1.1166x; 1.0090x over previous
#include <cuda_runtime.h>
#include <cuda_fp16.h>
#include <math.h>
#include <stdint.h>

// Problem constants
#define BB   2
#define NN   2048
#define HIDD 2048
#define NH   16
#define NKV  4
#define DD   128
#define MQ   (BB*NN)        // 4096
#define DQ   (NH*DD)        // 2048
#define DKV  (NKV*DD)       // 512
#define NQKV (DQ + 2*DKV)   // 3072

// ---------------- device scratch ------------------------------------------
__device__ __half g_Xh  [(size_t)MQ * HIDD];
__device__ __half g_QKV [(size_t)MQ * NQKV];
__device__ __half g_AOh [(size_t)MQ * DQ];
__device__ __half g_WTa [(size_t)NQKV * HIDD];
__device__ __half g_WTo [(size_t)HIDD * DQ];
__device__ float  g_FLA [(size_t)MQ * HIDD];
__device__ int    g_cntFlash[32];   // per (b,qi) flash completion (16 each)
__device__ int    g_cntFla;         // fla blocks done (128)

// ---------------- helpers --------------------------------------------------
__device__ __forceinline__ void mma_h16(float* c, const uint32_t* a, const uint32_t* b) {
    asm volatile(
        "mma.sync.aligned.m16n8k16.row.col.f32.f16.f16.f32 "
        "{%0,%1,%2,%3}, {%4,%5,%6,%7}, {%8,%9}, {%0,%1,%2,%3};\n"
        : "+f"(c[0]), "+f"(c[1]), "+f"(c[2]), "+f"(c[3])
        : "r"(a[0]), "r"(a[1]), "r"(a[2]), "r"(a[3]),
          "r"(b[0]), "r"(b[1]));
}
__device__ __forceinline__ void ldsm4(uint32_t& r0, uint32_t& r1, uint32_t& r2,
                                      uint32_t& r3, uint32_t addr) {
    asm volatile("ldmatrix.sync.aligned.m8n8.x4.shared.b16 {%0,%1,%2,%3}, [%4];"
                 : "=r"(r0), "=r"(r1), "=r"(r2), "=r"(r3) : "r"(addr));
}
__device__ __forceinline__ void cp16(void* smem, const void* gmem) {
    uint32_t s = (uint32_t)__cvta_generic_to_shared(smem);
    asm volatile("cp.async.cg.shared.global [%0], [%1], 16;\n" :: "r"(s), "l"(gmem));
}
__device__ __forceinline__ void cp_commit() { asm volatile("cp.async.commit_group;\n"); }
template<int N8>
__device__ __forceinline__ void cp_wait() { asm volatile("cp.async.wait_group %0;\n" :: "n"(N8)); }
__device__ __forceinline__ uint32_t h2u(__half2 h) { return *reinterpret_cast<uint32_t*>(&h); }

// ---------------- merged prepass kernel ------------------------------------
#define PB_CONV 8192
#define PB_WQ   4096
#define PB_WKV  1024
#define PB_WO   4096
#define PREP_BLOCKS (PB_CONV + PB_WQ + 2*PB_WKV + PB_WO + 1)

__device__ __forceinline__ void transh_dev(const float* __restrict__ W,
        __half* __restrict__ WT, int K, int N, float alpha, int bx, int by,
        float (*t)[33])
{
    int k0 = by * 32, n0 = bx * 32;
    int tx = threadIdx.x & 31, ty = threadIdx.x >> 5;
#pragma unroll
    for (int i = 0; i < 4; i++)
        t[ty + 8 * i][tx] = W[(long)(k0 + ty + 8 * i) * N + n0 + tx];
    __syncthreads();
#pragma unroll
    for (int i = 0; i < 4; i++)
        WT[(long)(n0 + ty + 8 * i) * K + k0 + tx] = __float2half_rn(alpha * t[tx][ty + 8 * i]);
}

__global__ __launch_bounds__(256)
void prep_k(const float* __restrict__ hid,
            const float* __restrict__ Wq, const float* __restrict__ Wk,
            const float* __restrict__ Wv, const float* __restrict__ Wo,
            __half* __restrict__ Xh, __half* __restrict__ WTa,
            __half* __restrict__ WTo, float scale)
{
    __shared__ float t[32][33];
    const int bid = blockIdx.x;

    if (bid < PB_CONV) {
        int i = bid * 256 + threadIdx.x;
        float4 v = ((const float4*)hid)[i];
        uint2 o;
        o.x = h2u(__floats2half2_rn(v.x, v.y));
        o.y = h2u(__floats2half2_rn(v.z, v.w));
        ((uint2*)Xh)[i] = o;
    } else if (bid < PB_CONV + PB_WQ) {
        int tbid = bid - PB_CONV;
        transh_dev(Wq, WTa, HIDD, DQ, scale, tbid & 63, tbid >> 6, t);
    } else if (bid < PB_CONV + PB_WQ + PB_WKV) {
        int tbid = bid - PB_CONV - PB_WQ;
        transh_dev(Wk, WTa + (size_t)DQ * HIDD, HIDD, DKV, 1.f,
                   tbid & 15, tbid >> 4, t);
    } else if (bid < PB_CONV + PB_WQ + 2 * PB_WKV) {
        int tbid = bid - PB_CONV - PB_WQ - PB_WKV;
        transh_dev(Wv, WTa + (size_t)(DQ + DKV) * HIDD, HIDD, DKV, 1.f,
                   tbid & 15, tbid >> 4, t);
    } else if (bid < PB_CONV + PB_WQ + 2 * PB_WKV + PB_WO) {
        int tbid = bid - PB_CONV - PB_WQ - 2 * PB_WKV;
        transh_dev(Wo, WTo, DQ, HIDD, 1.f, tbid & 63, tbid >> 6, t);
    } else {
        if (threadIdx.x < 32) g_cntFlash[threadIdx.x] = 0;
        if (threadIdx.x == 32) g_cntFla = 0;
    }
}

// ---------------- fp16 GEMM (standalone QKV projection, 2 CTAs/SM) --------
#define HP    20
#define HSTGW (128*HP)
#define QSTG  3
#define GEMM_SMEMQ (QSTG*2*HSTGW*4)      // 61440 B -> 2 CTAs/SM

__global__ __launch_bounds__(256, 2)
void gemm_h(const __half* __restrict__ Ag, const __half* __restrict__ Bt,
            __half* __restrict__ Cg, int Kdim, int N, float alpha)
{
    extern __shared__ uint32_t smw[];
    uint32_t* Asb = smw;
    uint32_t* Bsb = smw + QSTG * HSTGW;
    const uint32_t abase = (uint32_t)__cvta_generic_to_shared(Asb);
    const uint32_t bbase = (uint32_t)__cvta_generic_to_shared(Bsb);

    const int bx = blockIdx.x, by = blockIdx.y;
    const int tid  = threadIdx.x;
    const int lane = tid & 31;
    const int wid  = tid >> 5;
    const int wm   = wid >> 2;
    const int wn   = wid & 3;
    const int gr   = lane >> 2;
    const int gc   = lane & 3;

    const int rowA0 = by * 128;
    const int colB0 = bx * 128;
    const int niter = Kdim / 32;

    const int lrow  = lane & 15;
    const int lcolw = (lane >> 4) * 4;
    const uint32_t aoff = (uint32_t)(((wm * 64 + lrow) * HP + lcolw) * 4);
    const uint32_t boff = (uint32_t)(((wn * 32 + lrow) * HP + lcolw) * 4);

    const int r0 = tid >> 2,         s0 = (tid & 3);
    const int r1 = (tid + 256) >> 2, s1 = ((tid + 256) & 3);

#pragma unroll
    for (int s = 0; s < QSTG - 1; s++) {
        int k0 = s * 32;
        uint32_t* As = Asb + s * HSTGW;
        uint32_t* Bs = Bsb + s * HSTGW;
        cp16(&As[r0 * HP + s0 * 4], Ag + (size_t)(rowA0 + r0) * Kdim + k0 + s0 * 8);
        cp16(&As[r1 * HP + s1 * 4], Ag + (size_t)(rowA0 + r1) * Kdim + k0 + s1 * 8);
        cp16(&Bs[r0 * HP + s0 * 4], Bt + (size_t)(colB0 + r0) * Kdim + k0 + s0 * 8);
        cp16(&Bs[r1 * HP + s1 * 4], Bt + (size_t)(colB0 + r1) * Kdim + k0 + s1 * 8);
        cp_commit();
    }

    float acc[16][4];
#pragma unroll
    for (int i = 0; i < 16; i++)
#pragma unroll
        for (int j = 0; j < 4; j++) acc[i][j] = 0.f;

    for (int i = 0; i < niter; i++) {
        cp_wait<QSTG - 2>();
        __syncthreads();
        if (i + QSTG - 1 < niter) {
            int st = (i + QSTG - 1) % QSTG;
            int k0 = (i + QSTG - 1) * 32;
            uint32_t* As = Asb + st * HSTGW;
            uint32_t* Bs = Bsb + st * HSTGW;
            cp16(&As[r0 * HP + s0 * 4], Ag + (size_t)(rowA0 + r0) * Kdim + k0 + s0 * 8);
            cp16(&As[r1 * HP + s1 * 4], Ag + (size_t)(rowA0 + r1) * Kdim + k0 + s1 * 8);
            cp16(&Bs[r0 * HP + s0 * 4], Bt + (size_t)(colB0 + r0) * Kdim + k0 + s0 * 8);
            cp16(&Bs[r1 * HP + s1 * 4], Bt + (size_t)(colB0 + r1) * Kdim + k0 + s1 * 8);
        }
        cp_commit();

        const int cur = i % QSTG;
        const uint32_t ast = abase + (uint32_t)(cur * HSTGW * 4);
        const uint32_t bst = bbase + (uint32_t)(cur * HSTGW * 4);

#pragma unroll
        for (int ks = 0; ks < 2; ks++) {
            const int k2 = ks * 8;
            uint32_t a[4][4], bf[4][2];
#pragma unroll
            for (int mt = 0; mt < 4; mt++)
                ldsm4(a[mt][0], a[mt][1], a[mt][2], a[mt][3],
                      ast + aoff + (uint32_t)((mt * 16 * HP + k2) * 4));
#pragma unroll
            for (int p = 0; p < 2; p++) {
                uint32_t q0, q1, q2, q3;
                ldsm4(q0, q1, q2, q3, bst + boff + (uint32_t)((p * 16 * HP + k2) * 4));
                bf[2 * p][0] = q0;     bf[2 * p][1] = q2;
                bf[2 * p + 1][0] = q1; bf[2 * p + 1][1] = q3;
            }
#pragma unroll
            for (int mt = 0; mt < 4; mt++)
#pragma unroll
                for (int nt = 0; nt < 4; nt++)
                    mma_h16(acc[mt * 4 + nt], a[mt], bf[nt]);
        }
    }

#pragma unroll
    for (int mt = 0; mt < 4; mt++) {
        int row = rowA0 + wm * 64 + mt * 16 + gr;
#pragma unroll
        for (int nt = 0; nt < 4; nt++) {
            int col = colB0 + wn * 32 + nt * 8 + gc * 2;
            const float* ac = acc[mt * 4 + nt];
            *(uint32_t*)(Cg + (size_t)row * N + col) =
                h2u(__floats2half2_rn(ac[0], ac[1]));
            *(uint32_t*)(Cg + (size_t)(row + 8) * N + col) =
                h2u(__floats2half2_rn(ac[2], ac[3]));
        }
    }
}

// ---------------- fused attn + Wo kernel ----------------------------------
#define QPW 68
#define PPW2 36
#define NFLA 128
#define NFLASH 512
#define WSTG 4
#define WSTGW (128*HP)

struct FlashSmemH {
    uint32_t Qs[128 * QPW];
    uint32_t Kb[2][64 * QPW];
    uint32_t Vb[2][64 * QPW];
    uint32_t Ps[128 * PPW2];
    float red_m[4][128];
    float red_l[4][128];
};

struct FlaSmem {
    float ks[8][128];
    float gs[8][128];
    float qs[4][8][128];
    float vs[8][8];
    float os[8][4][8];
};

__device__ __forceinline__ void flash_pfkv(FlashSmemH* sm, int s,
        const __half* __restrict__ K, const __half* __restrict__ V,
        int b, int j, int tid)
{
#pragma unroll
    for (int it = 0; it < 4; it++) {
        int id = tid + it * 256;
        int r = id >> 4, seg = id & 15;
        size_t goff = (size_t)(b * NN + j * 64 + r) * NQKV + seg * 8;
        cp16(&sm->Kb[s][r * QPW + seg * 4], K + goff);
        cp16(&sm->Vb[s][r * QPW + seg * 4], V + goff);
    }
}

__device__ void fla_part(char* smbuf, const __half* Q, const __half* K,
                         const __half* V, int bid)
{
    FlaSmem* sm = (FlaSmem*)smbuf;
    const int et  = bid & 15;
    const int kvh = (bid >> 4) & 3;
    const int b   = bid >> 6;
    const int e0  = et * 8;
    const int tid = threadIdx.x;
    const int lane = tid & 31;
    const int w    = tid >> 5;

    float s0 = 0.f, s1 = 0.f, s2 = 0.f, s3 = 0.f;
    const float CSC = 0.01f;

    for (int c = 0; c < 256; c++) {
        const int n0 = c * 8;
#pragma unroll
        for (int i = 0; i < 4; i++) {
            int id = tid + i * 256;
            int hh = id >> 8, t = (id >> 5) & 7, d4 = (id & 31) * 4;
            uint2 raw = *(const uint2*)(Q + (size_t)(b * NN + n0 + t) * NQKV
                                          + (kvh * 4 + hh) * DD + d4);
            float2 f01 = __half22float2(*reinterpret_cast<__half2*>(&raw.x));
            float2 f23 = __half22float2(*reinterpret_cast<__half2*>(&raw.y));
            sm->qs[hh][t][d4 + 0] = f01.x; sm->qs[hh][t][d4 + 1] = f01.y;
            sm->qs[hh][t][d4 + 2] = f23.x; sm->qs[hh][t][d4 + 3] = f23.y;
        }
        {
            int t = tid >> 5, d4 = (tid & 31) * 4;
            uint2 raw = *(const uint2*)(K + (size_t)(b * NN + n0 + t) * NQKV
                                          + kvh * DD + d4);
            float2 f01 = __half22float2(*reinterpret_cast<__half2*>(&raw.x));
            float2 f23 = __half22float2(*reinterpret_cast<__half2*>(&raw.y));
            sm->ks[t][d4 + 0] = f01.x; sm->ks[t][d4 + 1] = f01.y;
            sm->ks[t][d4 + 2] = f23.x; sm->ks[t][d4 + 3] = f23.y;
            sm->gs[t][d4 + 0] = 1.f / (1.f + __expf(-f01.x));
            sm->gs[t][d4 + 1] = 1.f / (1.f + __expf(-f01.y));
            sm->gs[t][d4 + 2] = 1.f / (1.f + __expf(-f23.x));
            sm->gs[t][d4 + 3] = 1.f / (1.f + __expf(-f23.y));
        }
        if (tid < 64) {
            int t = tid >> 3, e = tid & 7;
            sm->vs[t][e] = __half2float(V[(size_t)(b * NN + n0 + t) * NQKV
                                          + kvh * DD + e0 + e]);
        }
        __syncthreads();

#pragma unroll
        for (int t = 0; t < 8; t++) {
            const float ve = sm->vs[t][w];
            const float g0 = sm->gs[t][lane],      g1 = sm->gs[t][lane + 32],
                        g2 = sm->gs[t][lane + 64], g3 = sm->gs[t][lane + 96];
            const float k0 = sm->ks[t][lane],      k1 = sm->ks[t][lane + 32],
                        k2 = sm->ks[t][lane + 64], k3 = sm->ks[t][lane + 96];
            s0 = s0 * g0 + k0 * ve;
            s1 = s1 * g1 + k1 * ve;
            s2 = s2 * g2 + k2 * ve;
            s3 = s3 * g3 + k3 * ve;
#pragma unroll
            for (int hh = 0; hh < 4; hh++) {
                float p = sm->qs[hh][t][lane]      * s0
                        + sm->qs[hh][t][lane + 32] * s1
                        + sm->qs[hh][t][lane + 64] * s2
                        + sm->qs[hh][t][lane + 96] * s3;
                p += __shfl_down_sync(0xffffffffu, p, 16);
                p += __shfl_down_sync(0xffffffffu, p, 8);
                p += __shfl_down_sync(0xffffffffu, p, 4);
                p += __shfl_down_sync(0xffffffffu, p, 2);
                p += __shfl_down_sync(0xffffffffu, p, 1);
                if (lane == 0) sm->os[t][hh][w] = p;
            }
        }
        __syncthreads();

        {
            int t = tid >> 5, hh = (tid >> 3) & 3, e = tid & 7;
            g_FLA[(size_t)(b * NN + n0 + t) * HIDD + (kvh * 4 + hh) * DD + e0 + e]
                = CSC * sm->os[t][hh][e];
        }
        __syncthreads();
    }

    if (tid == 0) { __threadfence(); atomicAdd(&g_cntFla, 1); }
}

__device__ void flash_part(char* smbuf, const __half* Q, const __half* K,
                           const __half* V, __half* AO, int bid2)
{
    FlashSmemH* sm = (FlashSmemH*)smbuf;

    const int bh = bid2 & 31;
    const int b  = bh >> 4, h = bh & 15;
    const int kvh = h >> 2;
    const int qi = 15 - (bid2 >> 5);

    const int tid  = threadIdx.x;
    const int lane = tid & 31;
    const int wid  = tid >> 5;
    const int wm   = wid >> 2;
    const int wn   = wid & 3;
    const int gr   = lane >> 2;
    const int gc   = lane & 3;

    const int nkv = 2 * qi + 2;
    const float LOG2E = 1.4426950408889634f;

    const __half* Kh = K + (size_t)kvh * DD;
    const __half* Vh = V + (size_t)kvh * DD;

    const int lrow  = lane & 15;
    const int lcolw = (lane >> 4) * 4;
    const uint32_t qfbase = (uint32_t)__cvta_generic_to_shared(sm->Qs)
                          + (uint32_t)(((wm * 64 + lrow) * QPW + lcolw) * 4);
    const uint32_t pfbase = (uint32_t)__cvta_generic_to_shared(sm->Ps)
                          + (uint32_t)(((wm * 64 + lrow) * PPW2 + lcolw) * 4);
    const uint32_t kfoff  = (uint32_t)(((wn * 16 + lrow) * QPW + lcolw) * 4);

#pragma unroll
    for (int it = 0; it < 8; it++) {
        int id = tid + it * 256;
        int r = id >> 4, seg = id & 15;
        cp16(&sm->Qs[r * QPW + seg * 4],
             Q + (size_t)(b * NN + qi * 128 + r) * NQKV + h * DD + seg * 8);
    }
    flash_pfkv(sm, 0, Kh, Vh, b, 0, tid);
    cp_commit();

    float mreg[4][2], lreg[4][2];
#pragma unroll
    for (int mt = 0; mt < 4; mt++)
#pragma unroll
        for (int hh = 0; hh < 2; hh++) { mreg[mt][hh] = -1e30f; lreg[mt][hh] = 0.f; }

    float acc_o[16][4];
#pragma unroll
    for (int i = 0; i < 16; i++)
#pragma unroll
        for (int j = 0; j < 4; j++) acc_o[i][j] = 0.f;

    for (int j = 0; j < nkv; j++) {
        const int s = j & 1;
        __syncthreads();
        if (j + 1 < nkv)
            flash_pfkv(sm, s ^ 1, Kh, Vh, b, j + 1, tid);
        cp_commit();
        cp_wait<1>();
        __syncthreads();

        const uint32_t kst = (uint32_t)__cvta_generic_to_shared(sm->Kb[s]) + kfoff;

        float acc_s[8][4];
#pragma unroll
        for (int i = 0; i < 8; i++)
#pragma unroll
            for (int c = 0; c < 4; c++) acc_s[i][c] = 0.f;

#pragma unroll
        for (int ks = 0; ks < 8; ks++) {
            const int k2 = ks * 8;
            uint32_t a[4][4], bfr[2][2];
#pragma unroll
            for (int mt = 0; mt < 4; mt++)
                ldsm4(a[mt][0], a[mt][1], a[mt][2], a[mt][3],
                      qfbase + (uint32_t)((mt * 16 * QPW + k2) * 4));
            {
                uint32_t q0, q1, q2, q3;
                ldsm4(q0, q1, q2, q3, kst + (uint32_t)(k2 * 4));
                bfr[0][0] = q0; bfr[0][1] = q2;
                bfr[1][0] = q1; bfr[1][1] = q3;
            }
#pragma unroll
            for (int mt = 0; mt < 4; mt++)
#pragma unroll
                for (int nt = 0; nt < 2; nt++)
                    mma_h16(acc_s[mt * 2 + nt], a[mt], bfr[nt]);
        }

        if ((j + 1) * 64 - 1 > qi * 128) {
#pragma unroll
            for (int mt = 0; mt < 4; mt++)
#pragma unroll
                for (int nt = 0; nt < 2; nt++)
#pragma unroll
                    for (int c = 0; c < 4; c++) {
                        int rowg = qi * 128 + wm * 64 + mt * 16 + gr + (c >> 1) * 8;
                        int colg = j * 64 + wn * 16 + nt * 8 + 2 * gc + (c & 1);
                        if (colg > rowg) acc_s[mt * 2 + nt][c] = -1e30f;
                    }
        }

#pragma unroll
        for (int mt = 0; mt < 4; mt++)
#pragma unroll
            for (int hh = 0; hh < 2; hh++) {
                float rmax = fmaxf(fmaxf(acc_s[mt * 2 + 0][hh * 2], acc_s[mt * 2 + 0][hh * 2 + 1]),
                                   fmaxf(acc_s[mt * 2 + 1][hh * 2], acc_s[mt * 2 + 1][hh * 2 + 1]));
                rmax = fmaxf(rmax, __shfl_xor_sync(0xffffffffu, rmax, 1));
                rmax = fmaxf(rmax, __shfl_xor_sync(0xffffffffu, rmax, 2));
                if (gc == 0)
                    sm->red_m[wn][wm * 64 + mt * 16 + gr + hh * 8] = rmax;
            }
        __syncthreads();

        float al[4][2];
#pragma unroll
        for (int mt = 0; mt < 4; mt++)
#pragma unroll
            for (int hh = 0; hh < 2; hh++) {
                int rl = wm * 64 + mt * 16 + gr + hh * 8;
                float m_old = mreg[mt][hh];
                float m_new = fmaxf(fmaxf(sm->red_m[0][rl], sm->red_m[1][rl]),
                                    fmaxf(sm->red_m[2][rl], sm->red_m[3][rl]));
                m_new = fmaxf(m_old, m_new);
                float alpha = exp2f((m_old - m_new) * LOG2E);
                al[mt][hh] = alpha;
                mreg[mt][hh] = m_new;
#pragma unroll
                for (int nt = 0; nt < 4; nt++) {
                    acc_o[mt * 4 + nt][hh * 2]     *= alpha;
                    acc_o[mt * 4 + nt][hh * 2 + 1] *= alpha;
                }
                float psum = 0.f;
#pragma unroll
                for (int nt = 0; nt < 2; nt++) {
                    float p0 = exp2f((acc_s[mt * 2 + nt][hh * 2]     - m_new) * LOG2E);
                    float p1 = exp2f((acc_s[mt * 2 + nt][hh * 2 + 1] - m_new) * LOG2E);
                    psum += p0 + p1;
                    sm->Ps[rl * PPW2 + wn * 8 + nt * 4 + gc] = h2u(__floats2half2_rn(p0, p1));
                }
                psum += __shfl_xor_sync(0xffffffffu, psum, 1);
                psum += __shfl_xor_sync(0xffffffffu, psum, 2);
                if (gc == 0) sm->red_l[wn][rl] = psum;
            }
        __syncthreads();

#pragma unroll
        for (int mt = 0; mt < 4; mt++)
#pragma unroll
            for (int hh = 0; hh < 2; hh++) {
                int rl = wm * 64 + mt * 16 + gr + hh * 8;
                lreg[mt][hh] = lreg[mt][hh] * al[mt][hh]
                             + sm->red_l[0][rl] + sm->red_l[1][rl]
                             + sm->red_l[2][rl] + sm->red_l[3][rl];
            }

        uint32_t vbase = (uint32_t)__cvta_generic_to_shared(&sm->Vb[s][0]);
        const int mrow = lane >> 3, rr = lane & 7;
#pragma unroll
        for (int ks = 0; ks < 4; ks++) {
            const int k2 = ks * 8;
            uint32_t pa[4][4];
#pragma unroll
            for (int mt = 0; mt < 4; mt++)
                ldsm4(pa[mt][0], pa[mt][1], pa[mt][2], pa[mt][3],
                      pfbase + (uint32_t)((mt * 16 * PPW2 + k2) * 4));
#pragma unroll
            for (int np = 0; np < 2; np++) {
                int n0 = wn * 32 + np * 16;
                int token = ks * 16 + (mrow & 1) * 8 + rr;
                int d     = n0 + (mrow >> 1) * 8;
                uint32_t addr = vbase + (uint32_t)(token * QPW + (d >> 1)) * 4;
                uint32_t v0, v1, v2, v3;
                asm volatile(
                    "ldmatrix.sync.aligned.m8n8.x4.trans.shared.b16 {%0,%1,%2,%3}, [%4];"
                    : "=r"(v0), "=r"(v1), "=r"(v2), "=r"(v3) : "r"(addr));
                uint32_t b0[2] = {v0, v1}, b1[2] = {v2, v3};
#pragma unroll
                for (int mt = 0; mt < 4; mt++) {
                    mma_h16(acc_o[mt * 4 + np * 2 + 0], pa[mt], b0);
                    mma_h16(acc_o[mt * 4 + np * 2 + 1], pa[mt], b1);
                }
            }
        }
    }

#pragma unroll
    for (int mt = 0; mt < 4; mt++)
#pragma unroll
        for (int hh = 0; hh < 2; hh++) {
            int rl = wm * 64 + mt * 16 + gr + hh * 8;
            float inv = 1.f / lreg[mt][hh];
            int gq = qi * 128 + rl;
#pragma unroll
            for (int nt = 0; nt < 4; nt++) {
                int col = wn * 32 + nt * 8 + 2 * gc;
                *(uint32_t*)(AO + (size_t)(b * NN + gq) * DQ + h * DD + col) =
                    h2u(__floats2half2_rn(acc_o[mt * 4 + nt][hh * 2] * inv,
                                          acc_o[mt * 4 + nt][hh * 2 + 1] * inv));
            }
        }

    __syncthreads();
    if (tid == 0) { __threadfence(); atomicAdd(&g_cntFlash[b * 16 + qi], 1); }
}

// Wo tile GEMM with spin dependencies: out = AO @ WTo^T + FLA
__device__ void wo_part(char* smbuf, const __half* __restrict__ Ag,
                        const __half* __restrict__ Bt,
                        float* __restrict__ outp, int bid3)
{
    const int rt = bid3 >> 4;
    const int ct = bid3 & 15;
    const int b  = rt & 1, qi = rt >> 1;

    const int tid  = threadIdx.x;

    if (tid == 0) {
        while (atomicAdd(&g_cntFlash[b * 16 + qi], 0) < 16) __nanosleep(256);
    }
    __syncthreads();
    __threadfence();

    uint32_t* smw = (uint32_t*)smbuf;
    uint32_t* Asb = smw;
    uint32_t* Bsb = smw + WSTG * WSTGW;
    const uint32_t abase = (uint32_t)__cvta_generic_to_shared(Asb);
    const uint32_t bbase = (uint32_t)__cvta_generic_to_shared(Bsb);

    const int lane = tid & 31;
    const int wid  = tid >> 5;
    const int wm   = wid >> 2;
    const int wn   = wid & 3;
    const int gr   = lane >> 2;
    const int gc   = lane & 3;

    const int Kdim = DQ;
    const int rowA0 = (b * NN + qi * 128);
    const int colB0 = ct * 128;
    const int niter = Kdim / 32;

    const int lrow  = lane & 15;
    const int lcolw = (lane >> 4) * 4;
    const uint32_t aoff = (uint32_t)(((wm * 64 + lrow) * HP + lcolw) * 4);
    const uint32_t boff = (uint32_t)(((wn * 32 + lrow) * HP + lcolw) * 4);

    const int r0 = tid >> 2,         s0 = (tid & 3);
    const int r1 = (tid + 256) >> 2, s1 = ((tid + 256) & 3);

#pragma unroll
    for (int s = 0; s < WSTG - 1; s++) {
        int k0 = s * 32;
        uint32_t* As = Asb + s * WSTGW;
        uint32_t* Bs = Bsb + s * WSTGW;
        cp16(&As[r0 * HP + s0 * 4], Ag + (size_t)(rowA0 + r0) * Kdim + k0 + s0 * 8);
        cp16(&As[r1 * HP + s1 * 4], Ag + (size_t)(rowA0 + r1) * Kdim + k0 + s1 * 8);
        cp16(&Bs[r0 * HP + s0 * 4], Bt + (size_t)(colB0 + r0) * Kdim + k0 + s0 * 8);
        cp16(&Bs[r1 * HP + s1 * 4], Bt + (size_t)(colB0 + r1) * Kdim + k0 + s1 * 8);
        cp_commit();
    }

    float acc[16][4];
#pragma unroll
    for (int i = 0; i < 16; i++)
#pragma unroll
        for (int j = 0; j < 4; j++) acc[i][j] = 0.f;

    for (int i = 0; i < niter; i++) {
        cp_wait<WSTG - 2>();
        __syncthreads();
        if (i + WSTG - 1 < niter) {
            int st = (i + WSTG - 1) & 3;
            int k0 = (i + WSTG - 1) * 32;
            uint32_t* As = Asb + st * WSTGW;
            uint32_t* Bs = Bsb + st * WSTGW;
            cp16(&As[r0 * HP + s0 * 4], Ag + (size_t)(rowA0 + r0) * Kdim + k0 + s0 * 8);
            cp16(&As[r1 * HP + s1 * 4], Ag + (size_t)(rowA0 + r1) * Kdim + k0 + s1 * 8);
            cp16(&Bs[r0 * HP + s0 * 4], Bt + (size_t)(colB0 + r0) * Kdim + k0 + s0 * 8);
            cp16(&Bs[r1 * HP + s1 * 4], Bt + (size_t)(colB0 + r1) * Kdim + k0 + s1 * 8);
        }
        cp_commit();

        const uint32_t ast = abase + (uint32_t)((i & 3) * WSTGW * 4);
        const uint32_t bst = bbase + (uint32_t)((i & 3) * WSTGW * 4);

#pragma unroll
        for (int ks = 0; ks < 2; ks++) {
            const int k2 = ks * 8;
            uint32_t a[4][4], bf[4][2];
#pragma unroll
            for (int mt = 0; mt < 4; mt++)
                ldsm4(a[mt][0], a[mt][1], a[mt][2], a[mt][3],
                      ast + aoff + (uint32_t)((mt * 16 * HP + k2) * 4));
#pragma unroll
            for (int p = 0; p < 2; p++) {
                uint32_t q0, q1, q2, q3;
                ldsm4(q0, q1, q2, q3, bst + boff + (uint32_t)((p * 16 * HP + k2) * 4));
                bf[2 * p][0] = q0;     bf[2 * p][1] = q2;
                bf[2 * p + 1][0] = q1; bf[2 * p + 1][1] = q3;
            }
#pragma unroll
            for (int mt = 0; mt < 4; mt++)
#pragma unroll
                for (int nt = 0; nt < 4; nt++)
                    mma_h16(acc[mt * 4 + nt], a[mt], bf[nt]);
        }
    }

    if (tid == 0) {
        while (atomicAdd(&g_cntFla, 0) < NFLA) __nanosleep(256);
    }
    __syncthreads();
    __threadfence();

#pragma unroll
    for (int mt = 0; mt < 4; mt++) {
        int row = rowA0 + wm * 64 + mt * 16 + gr;
#pragma unroll
        for (int nt = 0; nt < 4; nt++) {
            int col = colB0 + wn * 32 + nt * 8 + gc * 2;
            const float* ac = acc[mt * 4 + nt];
            const float* f0 = g_FLA + (size_t)row * HIDD + col;
            const float* f1 = g_FLA + (size_t)(row + 8) * HIDD + col;
            float2 rv0 = make_float2(ac[0] + f0[0], ac[1] + f0[1]);
            float2 rv1 = make_float2(ac[2] + f1[0], ac[3] + f1[1]);
            *(float2*)(outp + (size_t)row * HIDD + col) = rv0;
            *(float2*)(outp + (size_t)(row + 8) * HIDD + col) = rv1;
        }
    }
}

__global__ __launch_bounds__(256, 1)
void fused_all_k(const __half* __restrict__ Q, const __half* __restrict__ K,
                 const __half* __restrict__ V, __half* __restrict__ AO,
                 const __half* __restrict__ WTo, float* __restrict__ out)
{
    extern __shared__ char smbuf[];
    const int bid = blockIdx.x;
    if (bid < NFLA)
        fla_part(smbuf, Q, K, V, bid);
    else if (bid < NFLA + NFLASH)
        flash_part(smbuf, Q, K, V, AO, bid - NFLA);
    else
        wo_part(smbuf, AO, WTo, out, bid - NFLA - NFLASH);
}

// ---------------- launch ---------------------------------------------------
extern "C" void kernel_launch(void* const* d_in, const int* in_sizes, int n_in,
                              void* d_out, int out_size)
{
    const float* hid = (const float*)d_in[0];
    const float* Wq  = (const float*)d_in[1];
    const float* Wk  = (const float*)d_in[2];
    const float* Wv  = (const float*)d_in[3];
    const float* Wo  = (const float*)d_in[4];
    float* outp = (float*)d_out;

    __half *Xh, *QKV, *AOh, *WTa, *WTo;
    cudaGetSymbolAddress((void**)&Xh,  g_Xh);
    cudaGetSymbolAddress((void**)&QKV, g_QKV);
    cudaGetSymbolAddress((void**)&AOh, g_AOh);
    cudaGetSymbolAddress((void**)&WTa, g_WTa);
    cudaGetSymbolAddress((void**)&WTo, g_WTo);

    cudaFuncSetAttribute((const void*)gemm_h, cudaFuncAttributeMaxDynamicSharedMemorySize, GEMM_SMEMQ);
    cudaFuncSetAttribute((const void*)fused_all_k, cudaFuncAttributeMaxDynamicSharedMemorySize,
                         (int)sizeof(FlashSmemH));

    const float scale = 0.08838834764831845f;

    // single merged prepass: fp16 hidden + 4 weight transposes + counter reset
    prep_k<<<PREP_BLOCKS, 256>>>(hid, Wq, Wk, Wv, Wo, Xh, WTa, WTo, scale);

    // fused QKV projection (3-stage, 2 CTAs/SM)
    gemm_h<<<dim3(NQKV / 128, MQ / 128), 256, GEMM_SMEMQ>>>(
        Xh, WTa, QKV, HIDD, NQKV, 1.f);

    const __half* Qh = QKV;
    const __half* Kh = QKV + DQ;
    const __half* Vh = QKV + DQ + DKV;

    // FLA + flash + dependency-spun Wo, one launch
    fused_all_k<<<NFLA + NFLASH + 512, 256, sizeof(FlashSmemH)>>>(
        Qh, Kh, Vh, AOh, WTo, outp);
}